// round 7
// baseline (speedup 1.0000x reference)
#include <cuda_runtime.h>
#include <cuda_fp16.h>
#include <cstdint>
#include <cstddef>

// ---------------------------------------------------------------------------
// Problem constants
// ---------------------------------------------------------------------------
#define TOKENS   8192
#define IN_F     4096
#define OUT_F    4096
#define GS       128

// GEMM tiling (fp16): BK = 64 halves
#define BM 128
#define BN 128
#define BK 64
#define STAGES 4                      // B-only stages: 4 x 16KB = 64KB
#define NCHUNK (IN_F / BK)            // 64
#define GRID_N (OUT_F / BN)           // 32
#define GRID_M (TOKENS / BM)          // 64

#define STAGE_BYTES (BN * BK * 2)     // 16384 (B tile only; A comes via LDG)
#define GEMM_SMEM   (STAGES * STAGE_BYTES) // 65536

// ---------------------------------------------------------------------------
// Device scratch (static -- no cudaMalloc anywhere)
// g_x layout: row-major rows; within each row, each 64-col chunk is stored in
// MMA-fragment order:  byte_pos(k) = ((k>>1)&3)*32 + ((k>>4)&3)*8
//                                  + ((k>>3)&1)*4 + (k&1)*2
// so lane (g,t) reads its whole-chunk A data for one row as 32 contiguous
// bytes at offset t*32 (2 x LDG.128, dest regs == fragment regs).
// g_w layout: plain K-major (staged through smem + ldmatrix as before).
// ---------------------------------------------------------------------------
__device__ __half g_x[(size_t)TOKENS * IN_F];
__device__ __half g_w[(size_t)OUT_F * IN_F];
__device__ int    g_inv[IN_F];

// ---------------------------------------------------------------------------
// PTX helpers (family-common: mma.sync / ldmatrix / cp.async)
// ---------------------------------------------------------------------------
__device__ __forceinline__ uint32_t smem_u32(const void* p) {
    uint32_t a;
    asm("{ .reg .u64 t; cvta.to.shared.u64 t, %1; cvt.u32.u64 %0, t; }"
        : "=r"(a) : "l"(p));
    return a;
}

__device__ __forceinline__ void cp_async16(uint32_t smem_addr, const void* gptr) {
    asm volatile("cp.async.cg.shared.global [%0], [%1], 16;"
                 :: "r"(smem_addr),
                    "l"((unsigned long long)__cvta_generic_to_global(gptr))
                 : "memory");
}
#define CP_COMMIT() asm volatile("cp.async.commit_group;" ::: "memory")
#define CP_WAIT(n)  asm volatile("cp.async.wait_group %0;" :: "n"(n) : "memory")

#define LDSM4(r, addr)                                                         \
    asm volatile("ldmatrix.sync.aligned.m8n8.x4.shared.b16 {%0,%1,%2,%3}, [%4];" \
                 : "=r"((r)[0]), "=r"((r)[1]), "=r"((r)[2]), "=r"((r)[3])      \
                 : "r"(addr))

// m16n8k16 fp16 MMA, fp32 accumulate; a given as 4 scalar regs.
#define MMA_F16(d, a0, a1, a2, a3, b0, b1)                                     \
    asm volatile(                                                              \
        "mma.sync.aligned.m16n8k16.row.col.f32.f16.f16.f32 "                   \
        "{%0,%1,%2,%3}, {%4,%5,%6,%7}, {%8,%9}, {%0,%1,%2,%3};"                \
        : "+f"((d)[0]), "+f"((d)[1]), "+f"((d)[2]), "+f"((d)[3])               \
        : "r"(a0), "r"(a1), "r"(a2), "r"(a3), "r"(b0), "r"(b1))

// byte position of column k (0..63) inside a fragment-ordered 64-col chunk
__device__ __forceinline__ int pos64(int k) {
    return (((k >> 1) & 3) << 5) + (((k >> 4) & 3) << 3) +
           (((k >> 3) & 1) << 2) + ((k & 1) << 1);
}

// ---------------------------------------------------------------------------
// Prep kernels
// ---------------------------------------------------------------------------
__global__ void inv_perm_kernel(const int* __restrict__ perm) {
    int j = blockIdx.x * blockDim.x + threadIdx.x;
    if (j < IN_F) g_inv[perm[j]] = j;
}

// Dequantize + fold activation permutation into W; round to fp16.
__global__ void prep_w_kernel(const int* __restrict__ wp, const float* __restrict__ ws) {
    __shared__ int   srow[IN_F / 2];
    __shared__ float sscale[IN_F / GS];
    int o = blockIdx.x;
    int tid = threadIdx.x;
    for (int i = tid; i < IN_F / 2; i += 256) srow[i] = wp[(size_t)o * (IN_F / 2) + i];
    if (tid < IN_F / GS) sscale[tid] = ws[(size_t)o * (IN_F / GS) + tid];
    __syncthreads();
    for (int k = tid; k < IN_F; k += 256) {
        int j = g_inv[k];                        // source (pre-perm) column
        int b = srow[j >> 1];
        int q = (((j & 1) ? (b >> 4) : b) & 0xF) - 8;
        float w = (float)q * sscale[j >> 7];     // group = j / 128
        g_w[(size_t)o * IN_F + k] = __float2half_rn(w);
    }
}

// Round x to fp16; store in fragment-ordered chunk layout.
__global__ void prep_x_kernel(const float4* __restrict__ x) {
    int i = blockIdx.x * blockDim.x + threadIdx.x;   // exact grid
    float4 v = x[i];
    int k0 = (i * 4) & 63;                           // pos within 64-col chunk
    size_t base = (size_t)i * 4 - k0;                // chunk base (flat index)
    char* cb = reinterpret_cast<char*>(g_x + base);
    *reinterpret_cast<__half2*>(cb + pos64(k0))     = __floats2half2_rn(v.x, v.y);
    *reinterpret_cast<__half2*>(cb + pos64(k0 + 2)) = __floats2half2_rn(v.z, v.w);
}

// ---------------------------------------------------------------------------
// GEMM: 128x128 CTA tile; B through 4-stage cp.async smem + ldmatrix;
// A direct from global (LDG.128 into fragment regs). Warp grid 4(M) x 2(N).
// B smem rows 128B; swizzle: (seg*16) ^ ((row&7)<<4). 2 CTAs/SM.
// ---------------------------------------------------------------------------
__device__ __forceinline__ void load_stage_b(uint32_t sbase, int s, int chunk,
                                             int n0, int tid) {
    uint32_t st = sbase + (uint32_t)s * STAGE_BYTES;
    const __half* gB = g_w + (size_t)n0 * IN_F + chunk * BK;
    #pragma unroll
    for (int it = 0; it < 4; ++it) {
        int u = tid + it * 256;                  // 0..1023
        int r = u >> 3, seg = u & 7;             // row, 16B-seg within 128B row
        uint32_t so = (uint32_t)(r * 128) + (uint32_t)((seg * 16) ^ ((r & 7) << 4));
        cp_async16(st + so, gB + (size_t)r * IN_F + seg * 8);
    }
}

__global__ void __launch_bounds__(256, 2)
gemm_kernel(const float* __restrict__ bias, float* __restrict__ out) {
    extern __shared__ char smem[];
    const uint32_t sbase = smem_u32(smem);
    const int tid  = threadIdx.x;
    const int wid  = tid >> 5;
    const int lane = tid & 31;
    const int bid  = blockIdx.x;
    const int n0 = (bid & (GRID_N - 1)) * BN;    // n-fast: W slab stays in L2
    const int m0 = (bid / GRID_N) * BM;

    const int wm = wid >> 1;                     // 0..3
    const int wn = wid & 1;                      // 0..1
    const int g  = lane >> 2;                    // 0..7
    const int t  = lane & 3;                     // 0..3

    // ldmatrix lane roles (B only)
    const int mtx = lane >> 3;                   // matrix index 0..3
    const int rr  = lane & 7;                    // row within matrix
    const uint32_t swz = (uint32_t)rr << 4;
    // B: matrix m -> rows (wn*64 + jp*16 + (m>>1)*8 + rr), k-half (m&1)
    const uint32_t bRowOff = (uint32_t)((wn * 64 + (mtx >> 1) * 8 + rr) * 128);
    const uint32_t kbB = (uint32_t)((mtx & 1) * 16);

    // A pointer: lane covers rows m0 + wm*32 + g + {0,8,16,24}; within a
    // chunk its 32B sit at byte offset t*32 -> uint4 index t*2 (+1).
    const uint4* pa = reinterpret_cast<const uint4*>(
                          g_x + (size_t)(m0 + wm * 32 + g) * IN_F) + t * 2;
    const int rowStride4 = 8 * IN_F / 8;         // 8 rows in uint4 units = 4096

    float acc[2][8][4];
    #pragma unroll
    for (int i = 0; i < 2; ++i)
        #pragma unroll
        for (int j = 0; j < 8; ++j)
            #pragma unroll
            for (int c = 0; c < 4; ++c) acc[i][j][c] = 0.0f;

    #pragma unroll
    for (int c = 0; c < STAGES - 1; ++c) {
        load_stage_b(sbase, c, c, n0, tid);
        CP_COMMIT();
    }

    int s_cons = 0, s_prod = STAGES - 1;

    #pragma unroll 1
    for (int i = 0; i < NCHUNK; ++i) {
        // Issue A loads for this chunk first -- they fly during the B wait
        // and barrier below. Af[s] = {ks0h0, ks0h1, ks1h0, ks1h1} (a), ks2/3 (b).
        uint4 Afa[4], Afb[4];
        #pragma unroll
        for (int s = 0; s < 4; ++s) {
            Afa[s] = pa[s * rowStride4 + i * 8];
            Afb[s] = pa[s * rowStride4 + i * 8 + 1];
        }

        CP_WAIT(STAGES - 2);                     // B chunk i resident
        __syncthreads();
        if (i + STAGES - 1 < NCHUNK) {
            load_stage_b(sbase, s_prod, i + STAGES - 1, n0, tid);
            if (++s_prod == STAGES) s_prod = 0;
        }
        CP_COMMIT();                             // keep group count consistent

        const uint32_t st = sbase + (uint32_t)s_cons * STAGE_BYTES;
        if (++s_cons == STAGES) s_cons = 0;

        #pragma unroll
        for (int ks = 0; ks < 4; ++ks) {         // k16 steps
            // A fragment regs for this ks: rows g / g+8 (mi0), g+16 / g+24 (mi1)
            uint32_t a00, a01, a02, a03, a10, a11, a12, a13;
            if (ks == 0) {
                a00 = Afa[0].x; a02 = Afa[0].y; a01 = Afa[1].x; a03 = Afa[1].y;
                a10 = Afa[2].x; a12 = Afa[2].y; a11 = Afa[3].x; a13 = Afa[3].y;
            } else if (ks == 1) {
                a00 = Afa[0].z; a02 = Afa[0].w; a01 = Afa[1].z; a03 = Afa[1].w;
                a10 = Afa[2].z; a12 = Afa[2].w; a11 = Afa[3].z; a13 = Afa[3].w;
            } else if (ks == 2) {
                a00 = Afb[0].x; a02 = Afb[0].y; a01 = Afb[1].x; a03 = Afb[1].y;
                a10 = Afb[2].x; a12 = Afb[2].y; a11 = Afb[3].x; a13 = Afb[3].y;
            } else {
                a00 = Afb[0].z; a02 = Afb[0].w; a01 = Afb[1].z; a03 = Afb[1].w;
                a10 = Afb[2].z; a12 = Afb[2].w; a11 = Afb[3].z; a13 = Afb[3].w;
            }
            const uint32_t colB = ((uint32_t)(ks * 32) + kbB) ^ swz;
            #pragma unroll
            for (int jp = 0; jp < 4; ++jp) {     // regs 0,1 = j even; 2,3 = j odd
                uint32_t bq[4];
                LDSM4(bq, st + bRowOff + (uint32_t)(jp * 16 * 128) + colB);
                MMA_F16(acc[0][jp * 2],     a00, a01, a02, a03, bq[0], bq[1]);
                MMA_F16(acc[1][jp * 2],     a10, a11, a12, a13, bq[0], bq[1]);
                MMA_F16(acc[0][jp * 2 + 1], a00, a01, a02, a03, bq[2], bq[3]);
                MMA_F16(acc[1][jp * 2 + 1], a10, a11, a12, a13, bq[2], bq[3]);
            }
        }
    }

    // Epilogue: c0/c1 at (row, 2t), c2/c3 at (row+8, 2t); add bias, float2 stores
    #pragma unroll
    for (int mi = 0; mi < 2; ++mi) {
        const int row0 = m0 + wm * 32 + mi * 16 + g;
        #pragma unroll
        for (int j = 0; j < 8; ++j) {
            const int col = n0 + wn * 64 + j * 8 + t * 2;
            const float2 b2 = *reinterpret_cast<const float2*>(bias + col);
            float2 v0, v1;
            v0.x = acc[mi][j][0] + b2.x;  v0.y = acc[mi][j][1] + b2.y;
            v1.x = acc[mi][j][2] + b2.x;  v1.y = acc[mi][j][3] + b2.y;
            *reinterpret_cast<float2*>(out + (size_t)row0 * OUT_F + col) = v0;
            *reinterpret_cast<float2*>(out + (size_t)(row0 + 8) * OUT_F + col) = v1;
        }
    }
}

// ---------------------------------------------------------------------------
// Launch
// ---------------------------------------------------------------------------
extern "C" void kernel_launch(void* const* d_in, const int* in_sizes, int n_in,
                              void* d_out, int out_size) {
    const float* x    = (const float*)d_in[0];
    const int*   wp   = (const int*)d_in[1];
    const float* ws   = (const float*)d_in[2];
    const int*   perm = (const int*)d_in[3];
    const float* bias = (const float*)d_in[4];
    float* out = (float*)d_out;

    inv_perm_kernel<<<IN_F / 256, 256>>>(perm);
    prep_w_kernel<<<OUT_F, 256>>>(wp, ws);
    prep_x_kernel<<<(TOKENS * (IN_F / 4)) / 256, 256>>>((const float4*)x);

    cudaFuncSetAttribute(gemm_kernel, cudaFuncAttributeMaxDynamicSharedMemorySize,
                         GEMM_SMEM);
    gemm_kernel<<<GRID_M * GRID_N, 256, GEMM_SMEM>>>(bias, out);
}

// round 8
// speedup vs baseline: 1.0640x; 1.0640x over previous
#include <cuda_runtime.h>
#include <cuda_fp16.h>
#include <cstdint>
#include <cstddef>

// ---------------------------------------------------------------------------
// Problem constants
// ---------------------------------------------------------------------------
#define TOKENS   8192
#define IN_F     4096
#define OUT_F    4096
#define GS       128

// GEMM tiling (fp16): BK = 64 halves
#define BM 128
#define BN 128
#define BK 64
#define STAGES 5                      // B-only stages: 5 x 16KB = 80KB/CTA
#define NCHUNK (IN_F / BK)            // 64
#define GRID_N (OUT_F / BN)           // 32
#define GRID_M (TOKENS / BM)          // 64

#define STAGE_BYTES (BN * BK * 2)     // 16384 (B only; A comes via LDG)
#define GEMM_SMEM   (STAGES * STAGE_BYTES) // 81920

// ---------------------------------------------------------------------------
// Device scratch (static -- no cudaMalloc anywhere)
// g_x layout: row-major rows; within each row, each 64-col chunk is stored in
// MMA-fragment order:  byte_pos(k) = ((k>>1)&3)*32 + ((k>>4)&3)*8
//                                  + ((k>>3)&1)*4 + (k&1)*2
// so lane (g,t) reads its whole-chunk A data for one row as 32 contiguous
// bytes at offset t*32 (2 x LDG.128, dest regs == fragment regs).
// g_w layout: plain K-major (staged through smem + ldmatrix).
// ---------------------------------------------------------------------------
__device__ __half g_x[(size_t)TOKENS * IN_F];
__device__ __half g_w[(size_t)OUT_F * IN_F];
__device__ int    g_inv[IN_F];

// ---------------------------------------------------------------------------
// PTX helpers (family-common: mma.sync / ldmatrix / cp.async)
// ---------------------------------------------------------------------------
__device__ __forceinline__ uint32_t smem_u32(const void* p) {
    uint32_t a;
    asm("{ .reg .u64 t; cvta.to.shared.u64 t, %1; cvt.u32.u64 %0, t; }"
        : "=r"(a) : "l"(p));
    return a;
}

__device__ __forceinline__ void cp_async16(uint32_t smem_addr, const void* gptr) {
    asm volatile("cp.async.cg.shared.global [%0], [%1], 16;"
                 :: "r"(smem_addr),
                    "l"((unsigned long long)__cvta_generic_to_global(gptr))
                 : "memory");
}
#define CP_COMMIT() asm volatile("cp.async.commit_group;" ::: "memory")
#define CP_WAIT(n)  asm volatile("cp.async.wait_group %0;" :: "n"(n) : "memory")

#define LDSM4(r, addr)                                                         \
    asm volatile("ldmatrix.sync.aligned.m8n8.x4.shared.b16 {%0,%1,%2,%3}, [%4];" \
                 : "=r"((r)[0]), "=r"((r)[1]), "=r"((r)[2]), "=r"((r)[3])      \
                 : "r"(addr))

// m16n8k16 fp16 MMA, fp32 accumulate; a given as 4 scalar regs.
#define MMA_F16(d, a0, a1, a2, a3, b0, b1)                                     \
    asm volatile(                                                              \
        "mma.sync.aligned.m16n8k16.row.col.f32.f16.f16.f32 "                   \
        "{%0,%1,%2,%3}, {%4,%5,%6,%7}, {%8,%9}, {%0,%1,%2,%3};"                \
        : "+f"((d)[0]), "+f"((d)[1]), "+f"((d)[2]), "+f"((d)[3])               \
        : "r"(a0), "r"(a1), "r"(a2), "r"(a3), "r"(b0), "r"(b1))

// byte position of column k (0..63) inside a fragment-ordered 64-col chunk
__device__ __forceinline__ int pos64(int k) {
    return (((k >> 1) & 3) << 5) + (((k >> 4) & 3) << 3) +
           (((k >> 3) & 1) << 2) + ((k & 1) << 1);
}

// ---------------------------------------------------------------------------
// Prep kernels
// ---------------------------------------------------------------------------
__global__ void inv_perm_kernel(const int* __restrict__ perm) {
    int j = blockIdx.x * blockDim.x + threadIdx.x;
    if (j < IN_F) g_inv[perm[j]] = j;
}

// Dequantize + fold activation permutation into W; round to fp16.
__global__ void prep_w_kernel(const int* __restrict__ wp, const float* __restrict__ ws) {
    __shared__ int   srow[IN_F / 2];
    __shared__ float sscale[IN_F / GS];
    int o = blockIdx.x;
    int tid = threadIdx.x;
    for (int i = tid; i < IN_F / 2; i += 256) srow[i] = wp[(size_t)o * (IN_F / 2) + i];
    if (tid < IN_F / GS) sscale[tid] = ws[(size_t)o * (IN_F / GS) + tid];
    __syncthreads();
    for (int k = tid; k < IN_F; k += 256) {
        int j = g_inv[k];                        // source (pre-perm) column
        int b = srow[j >> 1];
        int q = (((j & 1) ? (b >> 4) : b) & 0xF) - 8;
        float w = (float)q * sscale[j >> 7];     // group = j / 128
        g_w[(size_t)o * IN_F + k] = __float2half_rn(w);
    }
}

// Round x to fp16; store in fragment-ordered chunk layout.
__global__ void prep_x_kernel(const float4* __restrict__ x) {
    int i = blockIdx.x * blockDim.x + threadIdx.x;   // exact grid
    float4 v = x[i];
    int k0 = (i * 4) & 63;                           // pos within 64-col chunk
    size_t base = (size_t)i * 4 - k0;                // chunk base (flat index)
    char* cb = reinterpret_cast<char*>(g_x + base);
    *reinterpret_cast<__half2*>(cb + pos64(k0))     = __floats2half2_rn(v.x, v.y);
    *reinterpret_cast<__half2*>(cb + pos64(k0 + 2)) = __floats2half2_rn(v.z, v.w);
}

// ---------------------------------------------------------------------------
// GEMM: 128x128 CTA tile; B through 5-stage cp.async smem + ldmatrix;
// A direct from global (LDG.128 with immediate offsets into fragment regs).
// Warp grid 4(M) x 2(N). B smem rows 128B; swizzle (seg*16)^((row&7)<<4).
// 2 CTAs/SM.
// ---------------------------------------------------------------------------
__device__ __forceinline__ void load_stage_b(uint32_t sbase, int s, int chunk,
                                             int n0, int tid) {
    uint32_t st = sbase + (uint32_t)s * STAGE_BYTES;
    const __half* gB = g_w + (size_t)n0 * IN_F + chunk * BK;
    #pragma unroll
    for (int it = 0; it < 4; ++it) {
        int u = tid + it * 256;                  // 0..1023
        int r = u >> 3, seg = u & 7;             // row, 16B-seg within 128B row
        uint32_t so = (uint32_t)(r * 128) + (uint32_t)((seg * 16) ^ ((r & 7) << 4));
        cp_async16(st + so, gB + (size_t)r * IN_F + seg * 8);
    }
}

__global__ void __launch_bounds__(256, 2)
gemm_kernel(const float* __restrict__ bias, float* __restrict__ out) {
    extern __shared__ char smem[];
    const uint32_t sbase = smem_u32(smem);
    const int tid  = threadIdx.x;
    const int wid  = tid >> 5;
    const int lane = tid & 31;
    const int bid  = blockIdx.x;
    const int n0 = (bid & (GRID_N - 1)) * BN;    // n-fast: W slab stays in L2
    const int m0 = (bid / GRID_N) * BM;

    const int wm = wid >> 1;                     // 0..3
    const int wn = wid & 1;                      // 0..1
    const int g  = lane >> 2;                    // 0..7
    const int t  = lane & 3;                     // 0..3

    // ldmatrix lane roles (B only)
    const int mtx = lane >> 3;                   // matrix index 0..3
    const int rr  = lane & 7;                    // row within matrix
    const uint32_t swz = (uint32_t)rr << 4;
    // B: matrix m -> rows (wn*64 + jp*16 + (m>>1)*8 + rr), k-half (m&1)
    const uint32_t bRowOff = (uint32_t)((wn * 64 + (mtx >> 1) * 8 + rr) * 128);
    const uint32_t kbB = (uint32_t)((mtx & 1) * 16);

    // A pointer: lane covers rows m0 + wm*32 + g + {0,8,16,24}; within a
    // chunk its 32B sit at byte offset t*32 -> uint4 index t*2.
    // Row +8 = +IN_F*2 bytes = +1024 uint4... (8 rows * 4096 cols * 2B / 16B
    // = 4096 uint4) -- compile-time constant offsets s*4096 below.
    const uint4* pa = reinterpret_cast<const uint4*>(
                          g_x + (size_t)(m0 + wm * 32 + g) * IN_F) + t * 2;

    float acc[2][8][4];
    #pragma unroll
    for (int i = 0; i < 2; ++i)
        #pragma unroll
        for (int j = 0; j < 8; ++j)
            #pragma unroll
            for (int c = 0; c < 4; ++c) acc[i][j][c] = 0.0f;

    #pragma unroll
    for (int c = 0; c < STAGES - 1; ++c) {
        load_stage_b(sbase, c, c, n0, tid);
        CP_COMMIT();
    }

    int s_cons = 0, s_prod = STAGES - 1;

    #pragma unroll 1
    for (int i = 0; i < NCHUNK; ++i) {
        // First A half (ks0/ks1): issue now; B-wait + barrier + B refill
        // below cover the latency. Constant offsets s*4096 (8 rows apart).
        uint4 Afa[4];
        Afa[0] = pa[0];
        Afa[1] = pa[4096];
        Afa[2] = pa[8192];
        Afa[3] = pa[12288];

        CP_WAIT(STAGES - 2);                     // B chunk i resident
        __syncthreads();
        if (i + STAGES - 1 < NCHUNK) {
            load_stage_b(sbase, s_prod, i + STAGES - 1, n0, tid);
            if (++s_prod == STAGES) s_prod = 0;
        }
        CP_COMMIT();                             // keep group count consistent

        // Second A half (ks2/ks3): in flight while ks0/ks1 compute.
        uint4 Afb[4];
        Afb[0] = pa[1];
        Afb[1] = pa[4097];
        Afb[2] = pa[8193];
        Afb[3] = pa[12289];
        pa += 8;                                 // next 64-col chunk

        const uint32_t st = sbase + (uint32_t)s_cons * STAGE_BYTES;
        if (++s_cons == STAGES) s_cons = 0;

        #pragma unroll
        for (int ks = 0; ks < 4; ++ks) {         // k16 steps
            uint32_t a00, a01, a02, a03, a10, a11, a12, a13;
            if (ks == 0) {
                a00 = Afa[0].x; a02 = Afa[0].y; a01 = Afa[1].x; a03 = Afa[1].y;
                a10 = Afa[2].x; a12 = Afa[2].y; a11 = Afa[3].x; a13 = Afa[3].y;
            } else if (ks == 1) {
                a00 = Afa[0].z; a02 = Afa[0].w; a01 = Afa[1].z; a03 = Afa[1].w;
                a10 = Afa[2].z; a12 = Afa[2].w; a11 = Afa[3].z; a13 = Afa[3].w;
            } else if (ks == 2) {
                a00 = Afb[0].x; a02 = Afb[0].y; a01 = Afb[1].x; a03 = Afb[1].y;
                a10 = Afb[2].x; a12 = Afb[2].y; a11 = Afb[3].x; a13 = Afb[3].y;
            } else {
                a00 = Afb[0].z; a02 = Afb[0].w; a01 = Afb[1].z; a03 = Afb[1].w;
                a10 = Afb[2].z; a12 = Afb[2].w; a11 = Afb[3].z; a13 = Afb[3].w;
            }
            const uint32_t colB = ((uint32_t)(ks * 32) + kbB) ^ swz;
            #pragma unroll
            for (int jp = 0; jp < 4; ++jp) {     // regs 0,1 = j even; 2,3 = j odd
                uint32_t bq[4];
                LDSM4(bq, st + bRowOff + (uint32_t)(jp * 16 * 128) + colB);
                MMA_F16(acc[0][jp * 2],     a00, a01, a02, a03, bq[0], bq[1]);
                MMA_F16(acc[1][jp * 2],     a10, a11, a12, a13, bq[0], bq[1]);
                MMA_F16(acc[0][jp * 2 + 1], a00, a01, a02, a03, bq[2], bq[3]);
                MMA_F16(acc[1][jp * 2 + 1], a10, a11, a12, a13, bq[2], bq[3]);
            }
        }
    }

    // Epilogue: c0/c1 at (row, 2t), c2/c3 at (row+8, 2t); add bias, float2 stores
    #pragma unroll
    for (int mi = 0; mi < 2; ++mi) {
        const int row0 = m0 + wm * 32 + mi * 16 + g;
        #pragma unroll
        for (int j = 0; j < 8; ++j) {
            const int col = n0 + wn * 64 + j * 8 + t * 2;
            const float2 b2 = *reinterpret_cast<const float2*>(bias + col);
            float2 v0, v1;
            v0.x = acc[mi][j][0] + b2.x;  v0.y = acc[mi][j][1] + b2.y;
            v1.x = acc[mi][j][2] + b2.x;  v1.y = acc[mi][j][3] + b2.y;
            *reinterpret_cast<float2*>(out + (size_t)row0 * OUT_F + col) = v0;
            *reinterpret_cast<float2*>(out + (size_t)(row0 + 8) * OUT_F + col) = v1;
        }
    }
}

// ---------------------------------------------------------------------------
// Launch
// ---------------------------------------------------------------------------
extern "C" void kernel_launch(void* const* d_in, const int* in_sizes, int n_in,
                              void* d_out, int out_size) {
    const float* x    = (const float*)d_in[0];
    const int*   wp   = (const int*)d_in[1];
    const float* ws   = (const float*)d_in[2];
    const int*   perm = (const int*)d_in[3];
    const float* bias = (const float*)d_in[4];
    float* out = (float*)d_out;

    inv_perm_kernel<<<IN_F / 256, 256>>>(perm);
    prep_w_kernel<<<OUT_F, 256>>>(wp, ws);
    prep_x_kernel<<<(TOKENS * (IN_F / 4)) / 256, 256>>>((const float4*)x);

    cudaFuncSetAttribute(gemm_kernel, cudaFuncAttributeMaxDynamicSharedMemorySize,
                         GEMM_SMEM);
    gemm_kernel<<<GRID_M * GRID_N, 256, GEMM_SMEM>>>(bias, out);
}

// round 9
// speedup vs baseline: 1.1381x; 1.0696x over previous
#include <cuda_runtime.h>
#include <cuda_fp16.h>
#include <cstdint>
#include <cstddef>

// ---------------------------------------------------------------------------
// Problem constants
// ---------------------------------------------------------------------------
#define TOKENS   8192
#define IN_F     4096
#define OUT_F    4096
#define GS       128

// GEMM tiling (fp16): BK = 64 halves = 128B rows
#define BM 128
#define BN 128
#define BK 64
#define STAGES 3                      // 96KB smem -> 2 CTAs/SM
#define NCHUNK (IN_F / BK)            // 64
#define GRID_N (OUT_F / BN)           // 32
#define GRID_M (TOKENS / BM)          // 64

#define OFF_B       (BM * BK * 2)     // 16384 (A tile bytes)
#define STAGE_BYTES ((BM + BN) * BK * 2)   // 32768
#define GEMM_SMEM   (STAGES * STAGE_BYTES) // 98304

// ---------------------------------------------------------------------------
// Device scratch (static -- no cudaMalloc anywhere)
// ---------------------------------------------------------------------------
__device__ __half g_x[(size_t)TOKENS * IN_F];   // x rounded to fp16
__device__ __half g_w[(size_t)OUT_F * IN_F];    // dequant + perm-folded fp16
__device__ int    g_inv[IN_F];

// ---------------------------------------------------------------------------
// PTX helpers (family-common: mma.sync / ldmatrix / cp.async)
// ---------------------------------------------------------------------------
__device__ __forceinline__ uint32_t smem_u32(const void* p) {
    uint32_t a;
    asm("{ .reg .u64 t; cvta.to.shared.u64 t, %1; cvt.u32.u64 %0, t; }"
        : "=r"(a) : "l"(p));
    return a;
}

__device__ __forceinline__ void cp_async16(uint32_t smem_addr, const void* gptr) {
    asm volatile("cp.async.cg.shared.global [%0], [%1], 16;"
                 :: "r"(smem_addr),
                    "l"((unsigned long long)__cvta_generic_to_global(gptr))
                 : "memory");
}
#define CP_COMMIT() asm volatile("cp.async.commit_group;" ::: "memory")
#define CP_WAIT(n)  asm volatile("cp.async.wait_group %0;" :: "n"(n) : "memory")

#define LDSM4(r, addr)                                                         \
    asm volatile("ldmatrix.sync.aligned.m8n8.x4.shared.b16 {%0,%1,%2,%3}, [%4];" \
                 : "=r"((r)[0]), "=r"((r)[1]), "=r"((r)[2]), "=r"((r)[3])      \
                 : "r"(addr))

// m16n8k16 fp16 MMA, fp32 accumulate.
#define MMA_F16(d, a, b0, b1)                                                  \
    asm volatile(                                                              \
        "mma.sync.aligned.m16n8k16.row.col.f32.f16.f16.f32 "                   \
        "{%0,%1,%2,%3}, {%4,%5,%6,%7}, {%8,%9}, {%0,%1,%2,%3};"                \
        : "+f"((d)[0]), "+f"((d)[1]), "+f"((d)[2]), "+f"((d)[3])               \
        : "r"((a)[0]), "r"((a)[1]), "r"((a)[2]), "r"((a)[3]),                  \
          "r"(b0), "r"(b1))

// ---------------------------------------------------------------------------
// Prep kernels
// ---------------------------------------------------------------------------
__global__ void inv_perm_kernel(const int* __restrict__ perm) {
    int j = blockIdx.x * blockDim.x + threadIdx.x;
    if (j < IN_F) g_inv[perm[j]] = j;
}

// Dequantize + fold activation permutation into W; round to fp16.
__global__ void prep_w_kernel(const int* __restrict__ wp, const float* __restrict__ ws) {
    __shared__ int   srow[IN_F / 2];
    __shared__ float sscale[IN_F / GS];
    int o = blockIdx.x;
    int tid = threadIdx.x;
    for (int i = tid; i < IN_F / 2; i += 256) srow[i] = wp[(size_t)o * (IN_F / 2) + i];
    if (tid < IN_F / GS) sscale[tid] = ws[(size_t)o * (IN_F / GS) + tid];
    __syncthreads();
    for (int k = tid; k < IN_F; k += 256) {
        int j = g_inv[k];                        // source (pre-perm) column
        int b = srow[j >> 1];
        int q = (((j & 1) ? (b >> 4) : b) & 0xF) - 8;
        float w = (float)q * sscale[j >> 7];     // group = j / 128
        g_w[(size_t)o * IN_F + k] = __float2half_rn(w);
    }
}

// Round x to fp16 once.
__global__ void prep_x_kernel(const float4* __restrict__ x) {
    int i = blockIdx.x * blockDim.x + threadIdx.x;   // exact grid
    float4 v = x[i];
    __half2 h0 = __floats2half2_rn(v.x, v.y);
    __half2 h1 = __floats2half2_rn(v.z, v.w);
    __half2* p = reinterpret_cast<__half2*>(g_x);
    p[2 * i]     = h0;
    p[2 * i + 1] = h1;
}

// ---------------------------------------------------------------------------
// GEMM: 128x128 CTA tile, 3-stage cp.async pipeline, m16n8k16 fp16 MMA,
// ldmatrix.x4 fragment loads with intra-chunk B double-buffering and the
// refill split into two halves to smooth crossbar pressure.
// Warp grid 4(M) x 2(N); warp tile 32x64. 2 CTAs/SM.
// smem rows are 128B (64 halves); swizzle: (seg*16) ^ ((row&7)<<4).
// ---------------------------------------------------------------------------
__device__ __forceinline__ void load_stage_half(uint32_t sbase, int s, int chunk,
                                                int m0, int n0, int tid, int half) {
    uint32_t st = sbase + (uint32_t)s * STAGE_BYTES;
    const __half* gA = g_x + (size_t)m0 * IN_F + chunk * BK;
    const __half* gB = g_w + (size_t)n0 * IN_F + chunk * BK;
    #pragma unroll
    for (int it = half * 2; it < half * 2 + 2; ++it) {
        int u = tid + it * 256;                  // 0..1023
        int r = u >> 3, seg = u & 7;             // row, 16B-seg within 128B row
        uint32_t so = (uint32_t)(r * 128) + (uint32_t)((seg * 16) ^ ((r & 7) << 4));
        cp_async16(st + so,         gA + (size_t)r * IN_F + seg * 8);
        cp_async16(st + OFF_B + so, gB + (size_t)r * IN_F + seg * 8);
    }
}

__global__ void __launch_bounds__(256, 2)
gemm_kernel(const float* __restrict__ bias, float* __restrict__ out) {
    extern __shared__ char smem[];
    const uint32_t sbase = smem_u32(smem);
    const int tid  = threadIdx.x;
    const int wid  = tid >> 5;
    const int lane = tid & 31;
    const int bid  = blockIdx.x;
    const int n0 = (bid & (GRID_N - 1)) * BN;    // n-fast: W slab stays in L2
    const int m0 = (bid / GRID_N) * BM;

    const int wm = wid >> 1;                     // 0..3
    const int wn = wid & 1;                      // 0..1
    const int g  = lane >> 2;                    // 0..7
    const int t  = lane & 3;                     // 0..3

    // ldmatrix lane roles
    const int mtx = lane >> 3;                   // matrix index 0..3
    const int rr  = lane & 7;                    // row within matrix
    const uint32_t swz = (uint32_t)rr << 4;      // XOR swizzle for this row

    // A: matrix m -> rows (wm*32 + mi*16 + (m&1)*8 + rr), k-half (m>>1)
    const uint32_t aRowOff = (uint32_t)((wm * 32 + (mtx & 1) * 8 + rr) * 128);
    const uint32_t kbA = (uint32_t)((mtx >> 1) * 16);
    // B: matrix m -> rows (wn*64 + jp*16 + (m>>1)*8 + rr), k-half (m&1)
    const uint32_t bRowOff = (uint32_t)((wn * 64 + (mtx >> 1) * 8 + rr) * 128) + OFF_B;
    const uint32_t kbB = (uint32_t)((mtx & 1) * 16);

    float acc[2][8][4];
    #pragma unroll
    for (int i = 0; i < 2; ++i)
        #pragma unroll
        for (int j = 0; j < 8; ++j)
            #pragma unroll
            for (int c = 0; c < 4; ++c) acc[i][j][c] = 0.0f;

    #pragma unroll
    for (int c = 0; c < STAGES - 1; ++c) {
        load_stage_half(sbase, c, c, m0, n0, tid, 0);
        load_stage_half(sbase, c, c, m0, n0, tid, 1);
        CP_COMMIT();
    }

    int s_cons = 0, s_prod = STAGES - 1;

    #pragma unroll 1
    for (int i = 0; i < NCHUNK; ++i) {
        CP_WAIT(STAGES - 2);                     // chunk i resident
        __syncthreads();
        const bool refill = (i + STAGES - 1 < NCHUNK);
        // refill half 1 right after the barrier
        if (refill) load_stage_half(sbase, s_prod, i + STAGES - 1, m0, n0, tid, 0);

        const uint32_t st = sbase + (uint32_t)s_cons * STAGE_BYTES;
        if (++s_cons == STAGES) s_cons = 0;

        // --- intra-chunk pipelined k-steps: B fragments double-buffered ---
        uint32_t b0[4][4], b1[4][4];             // [jp][reg]
        uint32_t ar[2][4];

        // preload B for ks0
        #pragma unroll
        for (int jp = 0; jp < 4; ++jp)
            LDSM4(b0[jp], st + bRowOff + (uint32_t)(jp * 16 * 128) + (kbB ^ swz));

        #pragma unroll
        for (int ks = 0; ks < 4; ++ks) {
            uint32_t (*cur)[4] = (ks & 1) ? b1 : b0;
            uint32_t (*nxt)[4] = (ks & 1) ? b0 : b1;
            // prefetch next ks's B fragments (hidden under this ks's MMAs)
            if (ks < 3) {
                const uint32_t colBn = ((uint32_t)((ks + 1) * 32) + kbB) ^ swz;
                #pragma unroll
                for (int jp = 0; jp < 4; ++jp)
                    LDSM4(nxt[jp], st + bRowOff + (uint32_t)(jp * 16 * 128) + colBn);
            }
            // A fragments for this ks
            const uint32_t colA = ((uint32_t)(ks * 32) + kbA) ^ swz;
            LDSM4(ar[0], st + aRowOff + colA);
            LDSM4(ar[1], st + aRowOff + 16 * 128 + colA);

            // refill half 2 + commit mid-chunk (spread crossbar writes)
            if (ks == 2) {
                if (refill) {
                    load_stage_half(sbase, s_prod, i + STAGES - 1, m0, n0, tid, 1);
                    if (++s_prod == STAGES) s_prod = 0;
                }
                CP_COMMIT();
            }

            #pragma unroll
            for (int jp = 0; jp < 4; ++jp) {     // regs 0,1 = j even; 2,3 = j odd
                MMA_F16(acc[0][jp * 2],     ar[0], cur[jp][0], cur[jp][1]);
                MMA_F16(acc[1][jp * 2],     ar[1], cur[jp][0], cur[jp][1]);
                MMA_F16(acc[0][jp * 2 + 1], ar[0], cur[jp][2], cur[jp][3]);
                MMA_F16(acc[1][jp * 2 + 1], ar[1], cur[jp][2], cur[jp][3]);
            }
        }
    }

    // Epilogue: c0/c1 at (row, 2t), c2/c3 at (row+8, 2t); add bias, float2 stores
    #pragma unroll
    for (int mi = 0; mi < 2; ++mi) {
        const int row0 = m0 + wm * 32 + mi * 16 + g;
        #pragma unroll
        for (int j = 0; j < 8; ++j) {
            const int col = n0 + wn * 64 + j * 8 + t * 2;
            const float2 b2 = *reinterpret_cast<const float2*>(bias + col);
            float2 v0, v1;
            v0.x = acc[mi][j][0] + b2.x;  v0.y = acc[mi][j][1] + b2.y;
            v1.x = acc[mi][j][2] + b2.x;  v1.y = acc[mi][j][3] + b2.y;
            *reinterpret_cast<float2*>(out + (size_t)row0 * OUT_F + col) = v0;
            *reinterpret_cast<float2*>(out + (size_t)(row0 + 8) * OUT_F + col) = v1;
        }
    }
}

// ---------------------------------------------------------------------------
// Launch
// ---------------------------------------------------------------------------
extern "C" void kernel_launch(void* const* d_in, const int* in_sizes, int n_in,
                              void* d_out, int out_size) {
    const float* x    = (const float*)d_in[0];
    const int*   wp   = (const int*)d_in[1];
    const float* ws   = (const float*)d_in[2];
    const int*   perm = (const int*)d_in[3];
    const float* bias = (const float*)d_in[4];
    float* out = (float*)d_out;

    inv_perm_kernel<<<IN_F / 256, 256>>>(perm);
    prep_w_kernel<<<OUT_F, 256>>>(wp, ws);
    prep_x_kernel<<<(TOKENS * (IN_F / 4)) / 256, 256>>>((const float4*)x);

    cudaFuncSetAttribute(gemm_kernel, cudaFuncAttributeMaxDynamicSharedMemorySize,
                         GEMM_SMEM);
    gemm_kernel<<<GRID_M * GRID_N, 256, GEMM_SMEM>>>(bias, out);
}

// round 10
// speedup vs baseline: 1.1870x; 1.0430x over previous
#include <cuda_runtime.h>
#include <cuda_fp16.h>
#include <cstdint>
#include <cstddef>

// ---------------------------------------------------------------------------
// Problem constants
// ---------------------------------------------------------------------------
#define TOKENS   8192
#define IN_F     4096
#define OUT_F    4096
#define GS       128

// GEMM tiling (fp16): CTA 128x256, warp tile 64x64, BK = 64 halves
#define BM 128
#define BN 256
#define BK 64
#define STAGES 4
#define NCHUNK (IN_F / BK)            // 64
#define GRID_N (OUT_F / BN)           // 16
#define GRID_M (TOKENS / BM)          // 64

#define OFF_B       (BM * BK * 2)     // 16384 (A tile bytes)
#define STAGE_BYTES ((BM + BN) * BK * 2)   // 49152
#define GEMM_SMEM   (STAGES * STAGE_BYTES) // 196608 (1 CTA/SM)

// ---------------------------------------------------------------------------
// Device scratch (static -- no cudaMalloc anywhere)
// ---------------------------------------------------------------------------
__device__ __half g_x[(size_t)TOKENS * IN_F];   // x rounded to fp16
__device__ __half g_w[(size_t)OUT_F * IN_F];    // dequant + perm-folded fp16
__device__ int    g_inv[IN_F];

// ---------------------------------------------------------------------------
// PTX helpers (family-common: mma.sync / ldmatrix / cp.async)
// ---------------------------------------------------------------------------
__device__ __forceinline__ uint32_t smem_u32(const void* p) {
    uint32_t a;
    asm("{ .reg .u64 t; cvta.to.shared.u64 t, %1; cvt.u32.u64 %0, t; }"
        : "=r"(a) : "l"(p));
    return a;
}

__device__ __forceinline__ void cp_async16(uint32_t smem_addr, const void* gptr) {
    asm volatile("cp.async.cg.shared.global [%0], [%1], 16;"
                 :: "r"(smem_addr),
                    "l"((unsigned long long)__cvta_generic_to_global(gptr))
                 : "memory");
}
#define CP_COMMIT() asm volatile("cp.async.commit_group;" ::: "memory")
#define CP_WAIT(n)  asm volatile("cp.async.wait_group %0;" :: "n"(n) : "memory")

#define LDSM4(r, addr)                                                         \
    asm volatile("ldmatrix.sync.aligned.m8n8.x4.shared.b16 {%0,%1,%2,%3}, [%4];" \
                 : "=r"((r)[0]), "=r"((r)[1]), "=r"((r)[2]), "=r"((r)[3])      \
                 : "r"(addr))

// m16n8k16 fp16 MMA, fp32 accumulate.
#define MMA_F16(d, a, b0, b1)                                                  \
    asm volatile(                                                              \
        "mma.sync.aligned.m16n8k16.row.col.f32.f16.f16.f32 "                   \
        "{%0,%1,%2,%3}, {%4,%5,%6,%7}, {%8,%9}, {%0,%1,%2,%3};"                \
        : "+f"((d)[0]), "+f"((d)[1]), "+f"((d)[2]), "+f"((d)[3])               \
        : "r"((a)[0]), "r"((a)[1]), "r"((a)[2]), "r"((a)[3]),                  \
          "r"(b0), "r"(b1))

// ---------------------------------------------------------------------------
// Prep kernels
// ---------------------------------------------------------------------------
__global__ void inv_perm_kernel(const int* __restrict__ perm) {
    int j = blockIdx.x * blockDim.x + threadIdx.x;
    if (j < IN_F) g_inv[perm[j]] = j;
}

// Dequantize + fold activation permutation into W; round to fp16.
__global__ void prep_w_kernel(const int* __restrict__ wp, const float* __restrict__ ws) {
    __shared__ int   srow[IN_F / 2];
    __shared__ float sscale[IN_F / GS];
    int o = blockIdx.x;
    int tid = threadIdx.x;
    for (int i = tid; i < IN_F / 2; i += 256) srow[i] = wp[(size_t)o * (IN_F / 2) + i];
    if (tid < IN_F / GS) sscale[tid] = ws[(size_t)o * (IN_F / GS) + tid];
    __syncthreads();
    for (int k = tid; k < IN_F; k += 256) {
        int j = g_inv[k];                        // source (pre-perm) column
        int b = srow[j >> 1];
        int q = (((j & 1) ? (b >> 4) : b) & 0xF) - 8;
        float w = (float)q * sscale[j >> 7];     // group = j / 128
        g_w[(size_t)o * IN_F + k] = __float2half_rn(w);
    }
}

// Round x to fp16 once.
__global__ void prep_x_kernel(const float4* __restrict__ x) {
    int i = blockIdx.x * blockDim.x + threadIdx.x;   // exact grid
    float4 v = x[i];
    __half2 h0 = __floats2half2_rn(v.x, v.y);
    __half2 h1 = __floats2half2_rn(v.z, v.w);
    __half2* p = reinterpret_cast<__half2*>(g_x);
    p[2 * i]     = h0;
    p[2 * i + 1] = h1;
}

// ---------------------------------------------------------------------------
// GEMM: CTA 128x256, 8 warps, warp tile 64x64 (wm 0..1, wn 0..3).
// 4-stage cp.async pipeline; ldmatrix.x4; A+B fragments double-buffered
// across k-steps. 1 CTA/SM, high register budget.
// smem rows 128B; swizzle: (seg*16) ^ ((row&7)<<4). A rows 0..127, B rows
// 128..383 contiguous (single row index r covers both regions).
// ---------------------------------------------------------------------------
__device__ __forceinline__ void load_stage_half(uint32_t sbase, int s, int chunk,
                                                int m0, int n0, int tid, int half) {
    uint32_t st = sbase + (uint32_t)s * STAGE_BYTES;
    const __half* gA = g_x + (size_t)m0 * IN_F + chunk * BK;
    const __half* gB = g_w + (size_t)n0 * IN_F + chunk * BK;
    #pragma unroll
    for (int it = half * 6; it < half * 6 + 6; ++it) {
        int u = tid + it * 256;                  // 0..3071
        int r = u >> 3, seg = u & 7;             // row 0..383, 16B-seg
        uint32_t so = (uint32_t)(r * 128) + (uint32_t)((seg * 16) ^ ((r & 7) << 4));
        const __half* src = (r < BM) ? gA + (size_t)r * IN_F + seg * 8
                                     : gB + (size_t)(r - BM) * IN_F + seg * 8;
        cp_async16(st + so, src);
    }
}

__global__ void __launch_bounds__(256, 1)
gemm_kernel(const float* __restrict__ bias, float* __restrict__ out) {
    extern __shared__ char smem[];
    const uint32_t sbase = smem_u32(smem);
    const int tid  = threadIdx.x;
    const int wid  = tid >> 5;
    const int lane = tid & 31;
    const int bid  = blockIdx.x;
    const int n0 = (bid & (GRID_N - 1)) * BN;    // n-fast: W slab stays in L2
    const int m0 = (bid / GRID_N) * BM;

    const int wm = wid & 1;                      // 0..1 (64 M-rows each)
    const int wn = wid >> 1;                     // 0..3 (64 N-cols each)
    const int g  = lane >> 2;                    // 0..7
    const int t  = lane & 3;                     // 0..3

    // ldmatrix lane roles
    const int mtx = lane >> 3;                   // matrix index 0..3
    const int rr  = lane & 7;                    // row within matrix
    const uint32_t swz = (uint32_t)rr << 4;      // XOR swizzle for this row

    // A: matrix m -> rows (wm*64 + mi*16 + (m&1)*8 + rr), k-half (m>>1)
    const uint32_t aRowOff = (uint32_t)((wm * 64 + (mtx & 1) * 8 + rr) * 128);
    const uint32_t kbA = (uint32_t)((mtx >> 1) * 16);
    // B: matrix m -> rows (wn*64 + jp*16 + (m>>1)*8 + rr), k-half (m&1)
    const uint32_t bRowOff = (uint32_t)((wn * 64 + (mtx >> 1) * 8 + rr) * 128) + OFF_B;
    const uint32_t kbB = (uint32_t)((mtx & 1) * 16);

    float acc[4][8][4];                          // [mi][j][reg] = 128 regs
    #pragma unroll
    for (int i = 0; i < 4; ++i)
        #pragma unroll
        for (int j = 0; j < 8; ++j)
            #pragma unroll
            for (int c = 0; c < 4; ++c) acc[i][j][c] = 0.0f;

    #pragma unroll
    for (int c = 0; c < STAGES - 1; ++c) {
        load_stage_half(sbase, c, c, m0, n0, tid, 0);
        load_stage_half(sbase, c, c, m0, n0, tid, 1);
        CP_COMMIT();
    }

    int s_cons = 0, s_prod = STAGES - 1;

    #pragma unroll 1
    for (int i = 0; i < NCHUNK; ++i) {
        CP_WAIT(STAGES - 2);                     // chunk i resident
        __syncthreads();
        const bool refill = (i + STAGES - 1 < NCHUNK);
        if (refill) load_stage_half(sbase, s_prod, i + STAGES - 1, m0, n0, tid, 0);

        const uint32_t st = sbase + (uint32_t)s_cons * STAGE_BYTES;
        if (++s_cons == STAGES) s_cons = 0;

        // --- k-steps with A+B fragment double-buffering ---
        uint32_t A0[4][4], A1[4][4];             // [mi][reg]
        uint32_t B0[4][4], B1[4][4];             // [jp][reg]

        #pragma unroll
        for (int mi = 0; mi < 4; ++mi)
            LDSM4(A0[mi], st + aRowOff + (uint32_t)(mi * 16 * 128) + (kbA ^ swz));
        #pragma unroll
        for (int jp = 0; jp < 4; ++jp)
            LDSM4(B0[jp], st + bRowOff + (uint32_t)(jp * 16 * 128) + (kbB ^ swz));

        #pragma unroll
        for (int ks = 0; ks < 4; ++ks) {
            uint32_t (*Ac)[4] = (ks & 1) ? A1 : A0;
            uint32_t (*An)[4] = (ks & 1) ? A0 : A1;
            uint32_t (*Bc)[4] = (ks & 1) ? B1 : B0;
            uint32_t (*Bn)[4] = (ks & 1) ? B0 : B1;
            if (ks < 3) {                        // prefetch next k-step
                const uint32_t cA = ((uint32_t)((ks + 1) * 32) + kbA) ^ swz;
                const uint32_t cB = ((uint32_t)((ks + 1) * 32) + kbB) ^ swz;
                #pragma unroll
                for (int mi = 0; mi < 4; ++mi)
                    LDSM4(An[mi], st + aRowOff + (uint32_t)(mi * 16 * 128) + cA);
                #pragma unroll
                for (int jp = 0; jp < 4; ++jp)
                    LDSM4(Bn[jp], st + bRowOff + (uint32_t)(jp * 16 * 128) + cB);
            }
            if (ks == 2) {                       // spread refill writes
                if (refill) {
                    load_stage_half(sbase, s_prod, i + STAGES - 1, m0, n0, tid, 1);
                    if (++s_prod == STAGES) s_prod = 0;
                }
                CP_COMMIT();
            }
            #pragma unroll
            for (int jp = 0; jp < 4; ++jp)
                #pragma unroll
                for (int mi = 0; mi < 4; ++mi) {
                    MMA_F16(acc[mi][jp * 2],     Ac[mi], Bc[jp][0], Bc[jp][1]);
                    MMA_F16(acc[mi][jp * 2 + 1], Ac[mi], Bc[jp][2], Bc[jp][3]);
                }
        }
    }

    // Epilogue: c0/c1 at (row, 2t), c2/c3 at (row+8, 2t); add bias, float2 stores
    #pragma unroll
    for (int mi = 0; mi < 4; ++mi) {
        const int row0 = m0 + wm * 64 + mi * 16 + g;
        #pragma unroll
        for (int j = 0; j < 8; ++j) {
            const int col = n0 + wn * 64 + j * 8 + t * 2;
            const float2 b2 = *reinterpret_cast<const float2*>(bias + col);
            float2 v0, v1;
            v0.x = acc[mi][j][0] + b2.x;  v0.y = acc[mi][j][1] + b2.y;
            v1.x = acc[mi][j][2] + b2.x;  v1.y = acc[mi][j][3] + b2.y;
            *reinterpret_cast<float2*>(out + (size_t)row0 * OUT_F + col) = v0;
            *reinterpret_cast<float2*>(out + (size_t)(row0 + 8) * OUT_F + col) = v1;
        }
    }
}

// ---------------------------------------------------------------------------
// Launch
// ---------------------------------------------------------------------------
extern "C" void kernel_launch(void* const* d_in, const int* in_sizes, int n_in,
                              void* d_out, int out_size) {
    const float* x    = (const float*)d_in[0];
    const int*   wp   = (const int*)d_in[1];
    const float* ws   = (const float*)d_in[2];
    const int*   perm = (const int*)d_in[3];
    const float* bias = (const float*)d_in[4];
    float* out = (float*)d_out;

    inv_perm_kernel<<<IN_F / 256, 256>>>(perm);
    prep_w_kernel<<<OUT_F, 256>>>(wp, ws);
    prep_x_kernel<<<(TOKENS * (IN_F / 4)) / 256, 256>>>((const float4*)x);

    cudaFuncSetAttribute(gemm_kernel, cudaFuncAttributeMaxDynamicSharedMemorySize,
                         GEMM_SMEM);
    gemm_kernel<<<GRID_M * GRID_N, 256, GEMM_SMEM>>>(bias, out);
}

// round 11
// speedup vs baseline: 1.2508x; 1.0538x over previous
#include <cuda_runtime.h>
#include <cuda_fp16.h>
#include <cstdint>
#include <cstddef>

// ---------------------------------------------------------------------------
// Problem constants
// ---------------------------------------------------------------------------
#define TOKENS   8192
#define IN_F     4096
#define OUT_F    4096
#define GS       128

// GEMM tiling (fp16): CTA 128x128 with 4 warps (2x2), warp tile 64x64.
#define BM 128
#define BN 128
#define BK 64
#define STAGES 3
#define NCHUNK (IN_F / BK)            // 64
#define GRID_N (OUT_F / BN)           // 32
#define GRID_M (TOKENS / BM)          // 64

#define OFF_B       (BM * BK * 2)     // 16384 (A tile bytes)
#define STAGE_BYTES ((BM + BN) * BK * 2)   // 32768
#define GEMM_SMEM   (STAGES * STAGE_BYTES) // 98304 (2 CTAs/SM -> 192KB)

// ---------------------------------------------------------------------------
// Device scratch (static -- no cudaMalloc anywhere)
// ---------------------------------------------------------------------------
__device__ __half g_x[(size_t)TOKENS * IN_F];   // x rounded to fp16
__device__ __half g_w[(size_t)OUT_F * IN_F];    // dequant + perm-folded fp16
__device__ int    g_inv[IN_F];

// ---------------------------------------------------------------------------
// PTX helpers (family-common: mma.sync / ldmatrix / cp.async)
// ---------------------------------------------------------------------------
__device__ __forceinline__ uint32_t smem_u32(const void* p) {
    uint32_t a;
    asm("{ .reg .u64 t; cvta.to.shared.u64 t, %1; cvt.u32.u64 %0, t; }"
        : "=r"(a) : "l"(p));
    return a;
}

__device__ __forceinline__ void cp_async16(uint32_t smem_addr, const void* gptr) {
    asm volatile("cp.async.cg.shared.global [%0], [%1], 16;"
                 :: "r"(smem_addr),
                    "l"((unsigned long long)__cvta_generic_to_global(gptr))
                 : "memory");
}
#define CP_COMMIT() asm volatile("cp.async.commit_group;" ::: "memory")
#define CP_WAIT(n)  asm volatile("cp.async.wait_group %0;" :: "n"(n) : "memory")

#define LDSM4(r, addr)                                                         \
    asm volatile("ldmatrix.sync.aligned.m8n8.x4.shared.b16 {%0,%1,%2,%3}, [%4];" \
                 : "=r"((r)[0]), "=r"((r)[1]), "=r"((r)[2]), "=r"((r)[3])      \
                 : "r"(addr))

// m16n8k16 fp16 MMA, fp32 accumulate.
#define MMA_F16(d, a, b0, b1)                                                  \
    asm volatile(                                                              \
        "mma.sync.aligned.m16n8k16.row.col.f32.f16.f16.f32 "                   \
        "{%0,%1,%2,%3}, {%4,%5,%6,%7}, {%8,%9}, {%0,%1,%2,%3};"                \
        : "+f"((d)[0]), "+f"((d)[1]), "+f"((d)[2]), "+f"((d)[3])               \
        : "r"((a)[0]), "r"((a)[1]), "r"((a)[2]), "r"((a)[3]),                  \
          "r"(b0), "r"(b1))

// ---------------------------------------------------------------------------
// Prep kernels
// ---------------------------------------------------------------------------
__global__ void inv_perm_kernel(const int* __restrict__ perm) {
    int j = blockIdx.x * blockDim.x + threadIdx.x;
    if (j < IN_F) g_inv[perm[j]] = j;
}

// Dequantize + fold activation permutation into W; round to fp16.
__global__ void prep_w_kernel(const int* __restrict__ wp, const float* __restrict__ ws) {
    __shared__ int   srow[IN_F / 2];
    __shared__ float sscale[IN_F / GS];
    int o = blockIdx.x;
    int tid = threadIdx.x;
    for (int i = tid; i < IN_F / 2; i += 256) srow[i] = wp[(size_t)o * (IN_F / 2) + i];
    if (tid < IN_F / GS) sscale[tid] = ws[(size_t)o * (IN_F / GS) + tid];
    __syncthreads();
    for (int k = tid; k < IN_F; k += 256) {
        int j = g_inv[k];                        // source (pre-perm) column
        int b = srow[j >> 1];
        int q = (((j & 1) ? (b >> 4) : b) & 0xF) - 8;
        float w = (float)q * sscale[j >> 7];     // group = j / 128
        g_w[(size_t)o * IN_F + k] = __float2half_rn(w);
    }
}

// Round x to fp16 once.
__global__ void prep_x_kernel(const float4* __restrict__ x) {
    int i = blockIdx.x * blockDim.x + threadIdx.x;   // exact grid
    float4 v = x[i];
    __half2 h0 = __floats2half2_rn(v.x, v.y);
    __half2 h1 = __floats2half2_rn(v.z, v.w);
    __half2* p = reinterpret_cast<__half2*>(g_x);
    p[2 * i]     = h0;
    p[2 * i + 1] = h1;
}

// ---------------------------------------------------------------------------
// GEMM: CTA 128x128, 4 warps (wm 0..1 x wn 0..1), warp tile 64x64.
// 3-stage cp.async pipeline; ldmatrix.x4; A+B fragments double-buffered
// across k-steps. 2 CTAs/SM (128 thr each) -> staggered barriers.
// smem rows 128B; swizzle: (seg*16) ^ ((row&7)<<4). A rows 0..127 then B.
// ---------------------------------------------------------------------------
__device__ __forceinline__ void load_stage_half(uint32_t sbase, int s, int chunk,
                                                int m0, int n0, int tid, int half) {
    uint32_t st = sbase + (uint32_t)s * STAGE_BYTES;
    const __half* gA = g_x + (size_t)m0 * IN_F + chunk * BK;
    const __half* gB = g_w + (size_t)n0 * IN_F + chunk * BK;
    #pragma unroll
    for (int it = half * 8; it < half * 8 + 8; ++it) {
        int u = tid + it * 128;                  // 0..2047
        int r = u >> 3, seg = u & 7;             // row 0..255, 16B-seg
        uint32_t so = (uint32_t)(r * 128) + (uint32_t)((seg * 16) ^ ((r & 7) << 4));
        const __half* src = (r < BM) ? gA + (size_t)r * IN_F + seg * 8
                                     : gB + (size_t)(r - BM) * IN_F + seg * 8;
        cp_async16(st + so, src);
    }
}

__global__ void __launch_bounds__(128, 2)
gemm_kernel(const float* __restrict__ bias, float* __restrict__ out) {
    extern __shared__ char smem[];
    const uint32_t sbase = smem_u32(smem);
    const int tid  = threadIdx.x;
    const int wid  = tid >> 5;                   // 0..3
    const int lane = tid & 31;
    const int bid  = blockIdx.x;
    const int n0 = (bid & (GRID_N - 1)) * BN;    // n-fast: W slab stays in L2
    const int m0 = (bid / GRID_N) * BM;

    const int wm = wid & 1;                      // 0..1 (64 M-rows each)
    const int wn = wid >> 1;                     // 0..1 (64 N-cols each)
    const int g  = lane >> 2;                    // 0..7
    const int t  = lane & 3;                     // 0..3

    // ldmatrix lane roles
    const int mtx = lane >> 3;                   // matrix index 0..3
    const int rr  = lane & 7;                    // row within matrix
    const uint32_t swz = (uint32_t)rr << 4;      // XOR swizzle for this row

    // A: matrix m -> rows (wm*64 + mi*16 + (m&1)*8 + rr), k-half (m>>1)
    const uint32_t aRowOff = (uint32_t)((wm * 64 + (mtx & 1) * 8 + rr) * 128);
    const uint32_t kbA = (uint32_t)((mtx >> 1) * 16);
    // B: matrix m -> rows (wn*64 + jp*16 + (m>>1)*8 + rr), k-half (m&1)
    const uint32_t bRowOff = (uint32_t)((wn * 64 + (mtx >> 1) * 8 + rr) * 128) + OFF_B;
    const uint32_t kbB = (uint32_t)((mtx & 1) * 16);

    float acc[4][8][4];                          // [mi][j][reg] = 128 regs
    #pragma unroll
    for (int i = 0; i < 4; ++i)
        #pragma unroll
        for (int j = 0; j < 8; ++j)
            #pragma unroll
            for (int c = 0; c < 4; ++c) acc[i][j][c] = 0.0f;

    #pragma unroll
    for (int c = 0; c < STAGES - 1; ++c) {
        load_stage_half(sbase, c, c, m0, n0, tid, 0);
        load_stage_half(sbase, c, c, m0, n0, tid, 1);
        CP_COMMIT();
    }

    int s_cons = 0, s_prod = STAGES - 1;

    #pragma unroll 1
    for (int i = 0; i < NCHUNK; ++i) {
        CP_WAIT(STAGES - 2);                     // chunk i resident
        __syncthreads();
        const bool refill = (i + STAGES - 1 < NCHUNK);
        if (refill) load_stage_half(sbase, s_prod, i + STAGES - 1, m0, n0, tid, 0);

        const uint32_t st = sbase + (uint32_t)s_cons * STAGE_BYTES;
        if (++s_cons == STAGES) s_cons = 0;

        // --- k-steps with A+B fragment double-buffering ---
        uint32_t A0[4][4], A1[4][4];             // [mi][reg]
        uint32_t B0[4][4], B1[4][4];             // [jp][reg]

        #pragma unroll
        for (int mi = 0; mi < 4; ++mi)
            LDSM4(A0[mi], st + aRowOff + (uint32_t)(mi * 16 * 128) + (kbA ^ swz));
        #pragma unroll
        for (int jp = 0; jp < 4; ++jp)
            LDSM4(B0[jp], st + bRowOff + (uint32_t)(jp * 16 * 128) + (kbB ^ swz));

        #pragma unroll
        for (int ks = 0; ks < 4; ++ks) {
            uint32_t (*Ac)[4] = (ks & 1) ? A1 : A0;
            uint32_t (*An)[4] = (ks & 1) ? A0 : A1;
            uint32_t (*Bc)[4] = (ks & 1) ? B1 : B0;
            uint32_t (*Bn)[4] = (ks & 1) ? B0 : B1;
            if (ks < 3) {                        // prefetch next k-step
                const uint32_t cA = ((uint32_t)((ks + 1) * 32) + kbA) ^ swz;
                const uint32_t cB = ((uint32_t)((ks + 1) * 32) + kbB) ^ swz;
                #pragma unroll
                for (int mi = 0; mi < 4; ++mi)
                    LDSM4(An[mi], st + aRowOff + (uint32_t)(mi * 16 * 128) + cA);
                #pragma unroll
                for (int jp = 0; jp < 4; ++jp)
                    LDSM4(Bn[jp], st + bRowOff + (uint32_t)(jp * 16 * 128) + cB);
            }
            if (ks == 2) {                       // spread refill writes
                if (refill) {
                    load_stage_half(sbase, s_prod, i + STAGES - 1, m0, n0, tid, 1);
                    if (++s_prod == STAGES) s_prod = 0;
                }
                CP_COMMIT();
            }
            #pragma unroll
            for (int jp = 0; jp < 4; ++jp)
                #pragma unroll
                for (int mi = 0; mi < 4; ++mi) {
                    MMA_F16(acc[mi][jp * 2],     Ac[mi], Bc[jp][0], Bc[jp][1]);
                    MMA_F16(acc[mi][jp * 2 + 1], Ac[mi], Bc[jp][2], Bc[jp][3]);
                }
        }
    }

    // Epilogue: c0/c1 at (row, 2t), c2/c3 at (row+8, 2t); add bias, float2 stores
    #pragma unroll
    for (int mi = 0; mi < 4; ++mi) {
        const int row0 = m0 + wm * 64 + mi * 16 + g;
        #pragma unroll
        for (int j = 0; j < 8; ++j) {
            const int col = n0 + wn * 64 + j * 8 + t * 2;
            const float2 b2 = *reinterpret_cast<const float2*>(bias + col);
            float2 v0, v1;
            v0.x = acc[mi][j][0] + b2.x;  v0.y = acc[mi][j][1] + b2.y;
            v1.x = acc[mi][j][2] + b2.x;  v1.y = acc[mi][j][3] + b2.y;
            *reinterpret_cast<float2*>(out + (size_t)row0 * OUT_F + col) = v0;
            *reinterpret_cast<float2*>(out + (size_t)(row0 + 8) * OUT_F + col) = v1;
        }
    }
}

// ---------------------------------------------------------------------------
// Launch
// ---------------------------------------------------------------------------
extern "C" void kernel_launch(void* const* d_in, const int* in_sizes, int n_in,
                              void* d_out, int out_size) {
    const float* x    = (const float*)d_in[0];
    const int*   wp   = (const int*)d_in[1];
    const float* ws   = (const float*)d_in[2];
    const int*   perm = (const int*)d_in[3];
    const float* bias = (const float*)d_in[4];
    float* out = (float*)d_out;

    inv_perm_kernel<<<IN_F / 256, 256>>>(perm);
    prep_w_kernel<<<OUT_F, 256>>>(wp, ws);
    prep_x_kernel<<<(TOKENS * (IN_F / 4)) / 256, 256>>>((const float4*)x);

    cudaFuncSetAttribute(gemm_kernel, cudaFuncAttributeMaxDynamicSharedMemorySize,
                         GEMM_SMEM);
    gemm_kernel<<<GRID_M * GRID_N, 128, GEMM_SMEM>>>(bias, out);
}

// round 12
// speedup vs baseline: 1.2685x; 1.0141x over previous
#include <cuda_runtime.h>
#include <cuda_fp16.h>
#include <cstdint>
#include <cstddef>

// ---------------------------------------------------------------------------
// Problem constants
// ---------------------------------------------------------------------------
#define TOKENS   8192
#define IN_F     4096
#define OUT_F    4096
#define GS       128

// GEMM tiling (fp16): BK = 64 halves = 128B rows
#define BM 128
#define BN 128
#define BK 64
#define STAGES 3                      // 96KB smem -> 2 CTAs/SM
#define NCHUNK (IN_F / BK)            // 64
#define GRID_N (OUT_F / BN)           // 32
#define GRID_M (TOKENS / BM)          // 64

#define OFF_B       (BM * BK * 2)     // 16384 (A tile bytes)
#define STAGE_BYTES ((BM + BN) * BK * 2)   // 32768
#define GEMM_SMEM   (STAGES * STAGE_BYTES) // 98304

// ---------------------------------------------------------------------------
// Device scratch (static -- no cudaMalloc anywhere)
// ---------------------------------------------------------------------------
__device__ __half g_x[(size_t)TOKENS * IN_F];   // x rounded to fp16
__device__ __half g_w[(size_t)OUT_F * IN_F];    // dequant + perm-folded fp16

// ---------------------------------------------------------------------------
// PTX helpers (family-common: mma.sync / ldmatrix / cp.async)
// ---------------------------------------------------------------------------
__device__ __forceinline__ uint32_t smem_u32(const void* p) {
    uint32_t a;
    asm("{ .reg .u64 t; cvta.to.shared.u64 t, %1; cvt.u32.u64 %0, t; }"
        : "=r"(a) : "l"(p));
    return a;
}

__device__ __forceinline__ void cp_async16(uint32_t smem_addr, const void* gptr) {
    asm volatile("cp.async.cg.shared.global [%0], [%1], 16;"
                 :: "r"(smem_addr),
                    "l"((unsigned long long)__cvta_generic_to_global(gptr))
                 : "memory");
}
#define CP_COMMIT() asm volatile("cp.async.commit_group;" ::: "memory")
#define CP_WAIT(n)  asm volatile("cp.async.wait_group %0;" :: "n"(n) : "memory")

#define LDSM4(r, addr)                                                         \
    asm volatile("ldmatrix.sync.aligned.m8n8.x4.shared.b16 {%0,%1,%2,%3}, [%4];" \
                 : "=r"((r)[0]), "=r"((r)[1]), "=r"((r)[2]), "=r"((r)[3])      \
                 : "r"(addr))

// m16n8k16 fp16 MMA, fp32 accumulate.
#define MMA_F16(d, a, b0, b1)                                                  \
    asm volatile(                                                              \
        "mma.sync.aligned.m16n8k16.row.col.f32.f16.f16.f32 "                   \
        "{%0,%1,%2,%3}, {%4,%5,%6,%7}, {%8,%9}, {%0,%1,%2,%3};"                \
        : "+f"((d)[0]), "+f"((d)[1]), "+f"((d)[2]), "+f"((d)[3])               \
        : "r"((a)[0]), "r"((a)[1]), "r"((a)[2]), "r"((a)[3]),                  \
          "r"(b0), "r"(b1))

// ---------------------------------------------------------------------------
// Fused prep kernel.
// Blocks [0, OUT_F): dequantize W row o, fold the activation permutation by
//   SCATTERING IN SMEM (g_w[o][perm[j]] = deq(w[o][j])), coalesced write-out.
//   No inverse-perm precomputation needed.
// Blocks [OUT_F, OUT_F+8192): convert a 1024-float4 slab of x to fp16.
// ---------------------------------------------------------------------------
__global__ void __launch_bounds__(256)
prep_kernel(const float4* __restrict__ x, const int* __restrict__ wp,
            const float* __restrict__ ws, const int* __restrict__ perm) {
    const int bid = blockIdx.x;
    const int tid = threadIdx.x;
    if (bid < OUT_F) {
        __shared__ int    sperm[IN_F];           // 16KB
        __shared__ int    srow[IN_F / 2];        // 8KB
        __shared__ float  sscale[IN_F / GS];     // 128B
        __shared__ __half sout[IN_F];            // 8KB
        for (int i = tid; i < IN_F; i += 256) sperm[i] = perm[i];
        for (int i = tid; i < IN_F / 2; i += 256)
            srow[i] = wp[(size_t)bid * (IN_F / 2) + i];
        if (tid < IN_F / GS) sscale[tid] = ws[(size_t)bid * (IN_F / GS) + tid];
        __syncthreads();
        for (int j = tid; j < IN_F; j += 256) {
            int b = srow[j >> 1];
            int q = (((j & 1) ? (b >> 4) : b) & 0xF) - 8;
            float w = (float)q * sscale[j >> 7];         // group = j / 128
            sout[sperm[j]] = __float2half_rn(w);         // smem scatter
        }
        __syncthreads();
        const int4* so4 = reinterpret_cast<const int4*>(sout);
        int4* go4 = reinterpret_cast<int4*>(g_w + (size_t)bid * IN_F);
        for (int i = tid; i < IN_F * 2 / 16; i += 256) go4[i] = so4[i];
    } else {
        const int xb = bid - OUT_F;                      // 0..8191
        const float4* src = x + (size_t)xb * 1024;
        __half2* dst = reinterpret_cast<__half2*>(g_x) + (size_t)xb * 2048;
        #pragma unroll
        for (int it = 0; it < 4; ++it) {
            int i = tid + it * 256;
            float4 v = src[i];
            dst[2 * i]     = __floats2half2_rn(v.x, v.y);
            dst[2 * i + 1] = __floats2half2_rn(v.z, v.w);
        }
    }
}

// ---------------------------------------------------------------------------
// GEMM: 128x128 CTA tile, 3-stage cp.async pipeline, m16n8k16 fp16 MMA,
// ldmatrix.x4 fragment loads; refill split into two halves (post-barrier and
// mid-chunk) to smooth crossbar pressure. Warp grid 4(M) x 2(N); warp tile
// 32x64. 2 CTAs/SM. smem rows 128B; swizzle: (seg*16) ^ ((row&7)<<4).
// ---------------------------------------------------------------------------
__device__ __forceinline__ void load_stage_half(uint32_t sbase, int s, int chunk,
                                                int m0, int n0, int tid, int half) {
    uint32_t st = sbase + (uint32_t)s * STAGE_BYTES;
    const __half* gA = g_x + (size_t)m0 * IN_F + chunk * BK;
    const __half* gB = g_w + (size_t)n0 * IN_F + chunk * BK;
    #pragma unroll
    for (int it = half * 2; it < half * 2 + 2; ++it) {
        int u = tid + it * 256;                  // 0..1023
        int r = u >> 3, seg = u & 7;             // row, 16B-seg within 128B row
        uint32_t so = (uint32_t)(r * 128) + (uint32_t)((seg * 16) ^ ((r & 7) << 4));
        cp_async16(st + so,         gA + (size_t)r * IN_F + seg * 8);
        cp_async16(st + OFF_B + so, gB + (size_t)r * IN_F + seg * 8);
    }
}

__global__ void __launch_bounds__(256, 2)
gemm_kernel(const float* __restrict__ bias, float* __restrict__ out) {
    extern __shared__ char smem[];
    const uint32_t sbase = smem_u32(smem);
    const int tid  = threadIdx.x;
    const int wid  = tid >> 5;
    const int lane = tid & 31;
    const int bid  = blockIdx.x;
    const int n0 = (bid & (GRID_N - 1)) * BN;    // n-fast: W slab stays in L2
    const int m0 = (bid / GRID_N) * BM;

    const int wm = wid >> 1;                     // 0..3
    const int wn = wid & 1;                      // 0..1
    const int g  = lane >> 2;                    // 0..7
    const int t  = lane & 3;                     // 0..3

    // ldmatrix lane roles
    const int mtx = lane >> 3;                   // matrix index 0..3
    const int rr  = lane & 7;                    // row within matrix
    const uint32_t swz = (uint32_t)rr << 4;      // XOR swizzle for this row

    // A: matrix m -> rows (wm*32 + mi*16 + (m&1)*8 + rr), k-half (m>>1)
    const uint32_t aRowOff = (uint32_t)((wm * 32 + (mtx & 1) * 8 + rr) * 128);
    const uint32_t kbA = (uint32_t)((mtx >> 1) * 16);
    // B: matrix m -> rows (wn*64 + jp*16 + (m>>1)*8 + rr), k-half (m&1)
    const uint32_t bRowOff = (uint32_t)((wn * 64 + (mtx >> 1) * 8 + rr) * 128) + OFF_B;
    const uint32_t kbB = (uint32_t)((mtx & 1) * 16);

    float acc[2][8][4];
    #pragma unroll
    for (int i = 0; i < 2; ++i)
        #pragma unroll
        for (int j = 0; j < 8; ++j)
            #pragma unroll
            for (int c = 0; c < 4; ++c) acc[i][j][c] = 0.0f;

    #pragma unroll
    for (int c = 0; c < STAGES - 1; ++c) {
        load_stage_half(sbase, c, c, m0, n0, tid, 0);
        load_stage_half(sbase, c, c, m0, n0, tid, 1);
        CP_COMMIT();
    }

    int s_cons = 0, s_prod = STAGES - 1;

    #pragma unroll 1
    for (int i = 0; i < NCHUNK; ++i) {
        CP_WAIT(STAGES - 2);                     // chunk i resident
        __syncthreads();
        const bool refill = (i + STAGES - 1 < NCHUNK);
        if (refill) load_stage_half(sbase, s_prod, i + STAGES - 1, m0, n0, tid, 0);

        const uint32_t st = sbase + (uint32_t)s_cons * STAGE_BYTES;
        if (++s_cons == STAGES) s_cons = 0;

        #pragma unroll
        for (int ks = 0; ks < 4; ++ks) {         // k16 steps; 32B per step
            if (ks == 2) {                       // second refill half + commit
                if (refill) {
                    load_stage_half(sbase, s_prod, i + STAGES - 1, m0, n0, tid, 1);
                    if (++s_prod == STAGES) s_prod = 0;
                }
                CP_COMMIT();
            }
            const uint32_t colA = ((uint32_t)(ks * 32) + kbA) ^ swz;
            const uint32_t colB = ((uint32_t)(ks * 32) + kbB) ^ swz;
            uint32_t ar[2][4];
            LDSM4(ar[0], st + aRowOff + colA);              // mi=0 (rows +0)
            LDSM4(ar[1], st + aRowOff + 16 * 128 + colA);   // mi=1 (rows +16)
            #pragma unroll
            for (int jp = 0; jp < 4; ++jp) {     // regs 0,1 = j even; 2,3 = j odd
                uint32_t bq[4];
                LDSM4(bq, st + bRowOff + (uint32_t)(jp * 16 * 128) + colB);
                MMA_F16(acc[0][jp * 2],     ar[0], bq[0], bq[1]);
                MMA_F16(acc[1][jp * 2],     ar[1], bq[0], bq[1]);
                MMA_F16(acc[0][jp * 2 + 1], ar[0], bq[2], bq[3]);
                MMA_F16(acc[1][jp * 2 + 1], ar[1], bq[2], bq[3]);
            }
        }
    }

    // Epilogue: c0/c1 at (row, 2t), c2/c3 at (row+8, 2t); add bias, float2 stores
    #pragma unroll
    for (int mi = 0; mi < 2; ++mi) {
        const int row0 = m0 + wm * 32 + mi * 16 + g;
        #pragma unroll
        for (int j = 0; j < 8; ++j) {
            const int col = n0 + wn * 64 + j * 8 + t * 2;
            const float2 b2 = *reinterpret_cast<const float2*>(bias + col);
            float2 v0, v1;
            v0.x = acc[mi][j][0] + b2.x;  v0.y = acc[mi][j][1] + b2.y;
            v1.x = acc[mi][j][2] + b2.x;  v1.y = acc[mi][j][3] + b2.y;
            *reinterpret_cast<float2*>(out + (size_t)row0 * OUT_F + col) = v0;
            *reinterpret_cast<float2*>(out + (size_t)(row0 + 8) * OUT_F + col) = v1;
        }
    }
}

// ---------------------------------------------------------------------------
// Launch
// ---------------------------------------------------------------------------
extern "C" void kernel_launch(void* const* d_in, const int* in_sizes, int n_in,
                              void* d_out, int out_size) {
    const float* x    = (const float*)d_in[0];
    const int*   wp   = (const int*)d_in[1];
    const float* ws   = (const float*)d_in[2];
    const int*   perm = (const int*)d_in[3];
    const float* bias = (const float*)d_in[4];
    float* out = (float*)d_out;

    // one fused prep launch: W blocks [0, OUT_F), x blocks [OUT_F, OUT_F+8192)
    prep_kernel<<<OUT_F + (TOKENS * IN_F / 4) / 1024, 256>>>(
        (const float4*)x, wp, ws, perm);

    cudaFuncSetAttribute(gemm_kernel, cudaFuncAttributeMaxDynamicSharedMemorySize,
                         GEMM_SMEM);
    gemm_kernel<<<GRID_M * GRID_N, 256, GEMM_SMEM>>>(bias, out);
}

// round 13
// speedup vs baseline: 1.2917x; 1.0183x over previous
#include <cuda_runtime.h>
#include <cuda_fp16.h>
#include <cstdint>
#include <cstddef>

// ---------------------------------------------------------------------------
// Problem constants
// ---------------------------------------------------------------------------
#define TOKENS   8192
#define IN_F     4096
#define OUT_F    4096
#define GS       128

// GEMM tiling (fp16): BK = 64 halves = 128B rows
#define BM 128
#define BN 128
#define BK 64
#define STAGES 3                      // 96KB smem -> 2 CTAs/SM
#define NCHUNK (IN_F / BK)            // 64
#define GRID_N (OUT_F / BN)           // 32
#define GRID_M (TOKENS / BM)          // 64

#define OFF_B       (BM * BK * 2)     // 16384 (A tile bytes)
#define STAGE_BYTES ((BM + BN) * BK * 2)   // 32768
#define GEMM_SMEM   (STAGES * STAGE_BYTES) // 98304

// ---------------------------------------------------------------------------
// Device scratch (static -- no cudaMalloc anywhere)
// ---------------------------------------------------------------------------
__device__ __half g_x[(size_t)TOKENS * IN_F];   // x rounded to fp16
__device__ __half g_w[(size_t)OUT_F * IN_F];    // dequant + perm-folded fp16
__device__ int    g_inv[IN_F];

// ---------------------------------------------------------------------------
// PTX helpers (family-common: mma.sync / ldmatrix / cp.async)
// ---------------------------------------------------------------------------
__device__ __forceinline__ uint32_t smem_u32(const void* p) {
    uint32_t a;
    asm("{ .reg .u64 t; cvta.to.shared.u64 t, %1; cvt.u32.u64 %0, t; }"
        : "=r"(a) : "l"(p));
    return a;
}

__device__ __forceinline__ void cp_async16(uint32_t smem_addr, const void* gptr) {
    asm volatile("cp.async.cg.shared.global [%0], [%1], 16;"
                 :: "r"(smem_addr),
                    "l"((unsigned long long)__cvta_generic_to_global(gptr))
                 : "memory");
}
#define CP_COMMIT() asm volatile("cp.async.commit_group;" ::: "memory")
#define CP_WAIT(n)  asm volatile("cp.async.wait_group %0;" :: "n"(n) : "memory")

#define LDSM4(r, addr)                                                         \
    asm volatile("ldmatrix.sync.aligned.m8n8.x4.shared.b16 {%0,%1,%2,%3}, [%4];" \
                 : "=r"((r)[0]), "=r"((r)[1]), "=r"((r)[2]), "=r"((r)[3])      \
                 : "r"(addr))

// m16n8k16 fp16 MMA, fp32 accumulate.
#define MMA_F16(d, a, b0, b1)                                                  \
    asm volatile(                                                              \
        "mma.sync.aligned.m16n8k16.row.col.f32.f16.f16.f32 "                   \
        "{%0,%1,%2,%3}, {%4,%5,%6,%7}, {%8,%9}, {%0,%1,%2,%3};"                \
        : "+f"((d)[0]), "+f"((d)[1]), "+f"((d)[2]), "+f"((d)[3])               \
        : "r"((a)[0]), "r"((a)[1]), "r"((a)[2]), "r"((a)[3]),                  \
          "r"(b0), "r"(b1))

// ---------------------------------------------------------------------------
// Prep kernels (R6 structure -- measured 65us; prep_x store micro-fix)
// ---------------------------------------------------------------------------
__global__ void inv_perm_kernel(const int* __restrict__ perm) {
    int j = blockIdx.x * blockDim.x + threadIdx.x;
    if (j < IN_F) g_inv[perm[j]] = j;
}

// Dequantize + fold activation permutation into W; round to fp16.
__global__ void prep_w_kernel(const int* __restrict__ wp, const float* __restrict__ ws) {
    __shared__ int   srow[IN_F / 2];
    __shared__ float sscale[IN_F / GS];
    int o = blockIdx.x;
    int tid = threadIdx.x;
    for (int i = tid; i < IN_F / 2; i += 256) srow[i] = wp[(size_t)o * (IN_F / 2) + i];
    if (tid < IN_F / GS) sscale[tid] = ws[(size_t)o * (IN_F / GS) + tid];
    __syncthreads();
    for (int k = tid; k < IN_F; k += 256) {
        int j = g_inv[k];                        // source (pre-perm) column
        int b = srow[j >> 1];
        int q = (((j & 1) ? (b >> 4) : b) & 0xF) - 8;
        float w = (float)q * sscale[j >> 7];     // group = j / 128
        g_w[(size_t)o * IN_F + k] = __float2half_rn(w);
    }
}

// Round x to fp16 once (float4 in -> one 8B store out).
__global__ void prep_x_kernel(const float4* __restrict__ x) {
    int i = blockIdx.x * blockDim.x + threadIdx.x;   // exact grid
    float4 v = x[i];
    __half2 h0 = __floats2half2_rn(v.x, v.y);
    __half2 h1 = __floats2half2_rn(v.z, v.w);
    uint2 packed;
    packed.x = *reinterpret_cast<uint32_t*>(&h0);
    packed.y = *reinterpret_cast<uint32_t*>(&h1);
    reinterpret_cast<uint2*>(g_x)[i] = packed;
}

// ---------------------------------------------------------------------------
// GEMM (R12 version -- measured 585.6us): 128x128 CTA tile, 3-stage cp.async
// pipeline, m16n8k16 fp16 MMA, ldmatrix.x4 fragment loads; refill split into
// two halves (post-barrier and mid-chunk) to smooth crossbar pressure.
// Warp grid 4(M) x 2(N); warp tile 32x64. 2 CTAs/SM.
// smem rows 128B; swizzle: (seg*16) ^ ((row&7)<<4).
// ---------------------------------------------------------------------------
__device__ __forceinline__ void load_stage_half(uint32_t sbase, int s, int chunk,
                                                int m0, int n0, int tid, int half) {
    uint32_t st = sbase + (uint32_t)s * STAGE_BYTES;
    const __half* gA = g_x + (size_t)m0 * IN_F + chunk * BK;
    const __half* gB = g_w + (size_t)n0 * IN_F + chunk * BK;
    #pragma unroll
    for (int it = half * 2; it < half * 2 + 2; ++it) {
        int u = tid + it * 256;                  // 0..1023
        int r = u >> 3, seg = u & 7;             // row, 16B-seg within 128B row
        uint32_t so = (uint32_t)(r * 128) + (uint32_t)((seg * 16) ^ ((r & 7) << 4));
        cp_async16(st + so,         gA + (size_t)r * IN_F + seg * 8);
        cp_async16(st + OFF_B + so, gB + (size_t)r * IN_F + seg * 8);
    }
}

__global__ void __launch_bounds__(256, 2)
gemm_kernel(const float* __restrict__ bias, float* __restrict__ out) {
    extern __shared__ char smem[];
    const uint32_t sbase = smem_u32(smem);
    const int tid  = threadIdx.x;
    const int wid  = tid >> 5;
    const int lane = tid & 31;
    const int bid  = blockIdx.x;
    const int n0 = (bid & (GRID_N - 1)) * BN;    // n-fast: W slab stays in L2
    const int m0 = (bid / GRID_N) * BM;

    const int wm = wid >> 1;                     // 0..3
    const int wn = wid & 1;                      // 0..1
    const int g  = lane >> 2;                    // 0..7
    const int t  = lane & 3;                     // 0..3

    // ldmatrix lane roles
    const int mtx = lane >> 3;                   // matrix index 0..3
    const int rr  = lane & 7;                    // row within matrix
    const uint32_t swz = (uint32_t)rr << 4;      // XOR swizzle for this row

    // A: matrix m -> rows (wm*32 + mi*16 + (m&1)*8 + rr), k-half (m>>1)
    const uint32_t aRowOff = (uint32_t)((wm * 32 + (mtx & 1) * 8 + rr) * 128);
    const uint32_t kbA = (uint32_t)((mtx >> 1) * 16);
    // B: matrix m -> rows (wn*64 + jp*16 + (m>>1)*8 + rr), k-half (m&1)
    const uint32_t bRowOff = (uint32_t)((wn * 64 + (mtx >> 1) * 8 + rr) * 128) + OFF_B;
    const uint32_t kbB = (uint32_t)((mtx & 1) * 16);

    float acc[2][8][4];
    #pragma unroll
    for (int i = 0; i < 2; ++i)
        #pragma unroll
        for (int j = 0; j < 8; ++j)
            #pragma unroll
            for (int c = 0; c < 4; ++c) acc[i][j][c] = 0.0f;

    #pragma unroll
    for (int c = 0; c < STAGES - 1; ++c) {
        load_stage_half(sbase, c, c, m0, n0, tid, 0);
        load_stage_half(sbase, c, c, m0, n0, tid, 1);
        CP_COMMIT();
    }

    int s_cons = 0, s_prod = STAGES - 1;

    #pragma unroll 1
    for (int i = 0; i < NCHUNK; ++i) {
        CP_WAIT(STAGES - 2);                     // chunk i resident
        __syncthreads();
        const bool refill = (i + STAGES - 1 < NCHUNK);
        if (refill) load_stage_half(sbase, s_prod, i + STAGES - 1, m0, n0, tid, 0);

        const uint32_t st = sbase + (uint32_t)s_cons * STAGE_BYTES;
        if (++s_cons == STAGES) s_cons = 0;

        #pragma unroll
        for (int ks = 0; ks < 4; ++ks) {         // k16 steps; 32B per step
            if (ks == 2) {                       // second refill half + commit
                if (refill) {
                    load_stage_half(sbase, s_prod, i + STAGES - 1, m0, n0, tid, 1);
                    if (++s_prod == STAGES) s_prod = 0;
                }
                CP_COMMIT();
            }
            const uint32_t colA = ((uint32_t)(ks * 32) + kbA) ^ swz;
            const uint32_t colB = ((uint32_t)(ks * 32) + kbB) ^ swz;
            uint32_t ar[2][4];
            LDSM4(ar[0], st + aRowOff + colA);              // mi=0 (rows +0)
            LDSM4(ar[1], st + aRowOff + 16 * 128 + colA);   // mi=1 (rows +16)
            #pragma unroll
            for (int jp = 0; jp < 4; ++jp) {     // regs 0,1 = j even; 2,3 = j odd
                uint32_t bq[4];
                LDSM4(bq, st + bRowOff + (uint32_t)(jp * 16 * 128) + colB);
                MMA_F16(acc[0][jp * 2],     ar[0], bq[0], bq[1]);
                MMA_F16(acc[1][jp * 2],     ar[1], bq[0], bq[1]);
                MMA_F16(acc[0][jp * 2 + 1], ar[0], bq[2], bq[3]);
                MMA_F16(acc[1][jp * 2 + 1], ar[1], bq[2], bq[3]);
            }
        }
    }

    // Epilogue: c0/c1 at (row, 2t), c2/c3 at (row+8, 2t); add bias, float2 stores
    #pragma unroll
    for (int mi = 0; mi < 2; ++mi) {
        const int row0 = m0 + wm * 32 + mi * 16 + g;
        #pragma unroll
        for (int j = 0; j < 8; ++j) {
            const int col = n0 + wn * 64 + j * 8 + t * 2;
            const float2 b2 = *reinterpret_cast<const float2*>(bias + col);
            float2 v0, v1;
            v0.x = acc[mi][j][0] + b2.x;  v0.y = acc[mi][j][1] + b2.y;
            v1.x = acc[mi][j][2] + b2.x;  v1.y = acc[mi][j][3] + b2.y;
            *reinterpret_cast<float2*>(out + (size_t)row0 * OUT_F + col) = v0;
            *reinterpret_cast<float2*>(out + (size_t)(row0 + 8) * OUT_F + col) = v1;
        }
    }
}

// ---------------------------------------------------------------------------
// Launch
// ---------------------------------------------------------------------------
extern "C" void kernel_launch(void* const* d_in, const int* in_sizes, int n_in,
                              void* d_out, int out_size) {
    const float* x    = (const float*)d_in[0];
    const int*   wp   = (const int*)d_in[1];
    const float* ws   = (const float*)d_in[2];
    const int*   perm = (const int*)d_in[3];
    const float* bias = (const float*)d_in[4];
    float* out = (float*)d_out;

    inv_perm_kernel<<<IN_F / 256, 256>>>(perm);
    prep_w_kernel<<<OUT_F, 256>>>(wp, ws);
    prep_x_kernel<<<(TOKENS * (IN_F / 4)) / 256, 256>>>((const float4*)x);

    cudaFuncSetAttribute(gemm_kernel, cudaFuncAttributeMaxDynamicSharedMemorySize,
                         GEMM_SMEM);
    gemm_kernel<<<GRID_M * GRID_N, 256, GEMM_SMEM>>>(bias, out);
}

// round 14
// speedup vs baseline: 1.3164x; 1.0191x over previous
#include <cuda_runtime.h>
#include <cuda_fp16.h>
#include <cstdint>
#include <cstddef>

// ---------------------------------------------------------------------------
// Problem constants
// ---------------------------------------------------------------------------
#define TOKENS   8192
#define IN_F     4096
#define OUT_F    4096
#define GS       128

// GEMM tiling (fp16): BK = 64 halves = 128B rows
#define BM 128
#define BN 128
#define BK 64
#define STAGES 3                      // 96KB smem -> 2 CTAs/SM
#define NCHUNK (IN_F / BK)            // 64
#define GRID_N (OUT_F / BN)           // 32
#define GRID_M (TOKENS / BM)          // 64

#define OFF_B       (BM * BK * 2)     // 16384 (A tile bytes)
#define STAGE_BYTES ((BM + BN) * BK * 2)   // 32768
#define GEMM_SMEM   (STAGES * STAGE_BYTES) // 98304

// ---------------------------------------------------------------------------
// Device scratch (static -- no cudaMalloc anywhere)
// ---------------------------------------------------------------------------
__device__ __half g_x[(size_t)TOKENS * IN_F];   // x rounded to fp16
__device__ __half g_w[(size_t)OUT_F * IN_F];    // dequant + perm-folded fp16
__device__ int    g_inv[IN_F];

// ---------------------------------------------------------------------------
// PTX helpers (family-common: mma.sync / ldmatrix / cp.async)
// ---------------------------------------------------------------------------
__device__ __forceinline__ uint32_t smem_u32(const void* p) {
    uint32_t a;
    asm("{ .reg .u64 t; cvta.to.shared.u64 t, %1; cvt.u32.u64 %0, t; }"
        : "=r"(a) : "l"(p));
    return a;
}

__device__ __forceinline__ void cp_async16(uint32_t smem_addr, const void* gptr) {
    asm volatile("cp.async.cg.shared.global [%0], [%1], 16;"
                 :: "r"(smem_addr),
                    "l"((unsigned long long)__cvta_generic_to_global(gptr))
                 : "memory");
}
#define CP_COMMIT() asm volatile("cp.async.commit_group;" ::: "memory")
#define CP_WAIT(n)  asm volatile("cp.async.wait_group %0;" :: "n"(n) : "memory")

#define LDSM4(r, addr)                                                         \
    asm volatile("ldmatrix.sync.aligned.m8n8.x4.shared.b16 {%0,%1,%2,%3}, [%4];" \
                 : "=r"((r)[0]), "=r"((r)[1]), "=r"((r)[2]), "=r"((r)[3])      \
                 : "r"(addr))

// m16n8k16 fp16 MMA, fp32 accumulate.
#define MMA_F16(d, a, b0, b1)                                                  \
    asm volatile(                                                              \
        "mma.sync.aligned.m16n8k16.row.col.f32.f16.f16.f32 "                   \
        "{%0,%1,%2,%3}, {%4,%5,%6,%7}, {%8,%9}, {%0,%1,%2,%3};"                \
        : "+f"((d)[0]), "+f"((d)[1]), "+f"((d)[2]), "+f"((d)[3])               \
        : "r"((a)[0]), "r"((a)[1]), "r"((a)[2]), "r"((a)[3]),                  \
          "r"(b0), "r"(b1))

// ---------------------------------------------------------------------------
// Prep: tiny inverse-perm kernel, then ONE fused kernel whose block ranges
// cover the W dequant (gather via g_inv, proven fast) and the x conversion
// (4 float4 per thread) so the two streams of work run concurrently.
// ---------------------------------------------------------------------------
__global__ void inv_perm_kernel(const int* __restrict__ perm) {
    int j = blockIdx.x * blockDim.x + threadIdx.x;
    if (j < IN_F) g_inv[perm[j]] = j;
}

#define XBLOCKS (TOKENS * IN_F / 4 / 1024)       // 8192 (1024 float4 per block)

__global__ void __launch_bounds__(256)
prep_kernel(const float4* __restrict__ x, const int* __restrict__ wp,
            const float* __restrict__ ws) {
    const int bid = blockIdx.x;
    const int tid = threadIdx.x;
    if (bid < OUT_F) {
        // --- W path: dequant + perm-fold (gather), fp16 ---
        __shared__ int   srow[IN_F / 2];
        __shared__ float sscale[IN_F / GS];
        for (int i = tid; i < IN_F / 2; i += 256)
            srow[i] = wp[(size_t)bid * (IN_F / 2) + i];
        if (tid < IN_F / GS) sscale[tid] = ws[(size_t)bid * (IN_F / GS) + tid];
        __syncthreads();
        for (int k = tid; k < IN_F; k += 256) {
            int j = g_inv[k];                    // source (pre-perm) column
            int b = srow[j >> 1];
            int q = (((j & 1) ? (b >> 4) : b) & 0xF) - 8;
            float w = (float)q * sscale[j >> 7]; // group = j / 128
            g_w[(size_t)bid * IN_F + k] = __float2half_rn(w);
        }
    } else {
        // --- x path: fp32 -> fp16, 4 float4 per thread ---
        const int xb = bid - OUT_F;              // 0..XBLOCKS-1
        const float4* src = x + (size_t)xb * 1024;
        uint2* dst = reinterpret_cast<uint2*>(g_x) + (size_t)xb * 1024;
        #pragma unroll
        for (int it = 0; it < 4; ++it) {
            int i = tid + it * 256;
            float4 v = src[i];
            __half2 h0 = __floats2half2_rn(v.x, v.y);
            __half2 h1 = __floats2half2_rn(v.z, v.w);
            uint2 packed;
            packed.x = *reinterpret_cast<uint32_t*>(&h0);
            packed.y = *reinterpret_cast<uint32_t*>(&h1);
            dst[i] = packed;
        }
    }
}

// ---------------------------------------------------------------------------
// GEMM (R13 version, measured 582.0us): 128x128 CTA tile, 3-stage cp.async
// pipeline, m16n8k16 fp16 MMA, ldmatrix.x4 fragment loads; refill split into
// two halves (post-barrier and mid-chunk). Warp grid 4(M) x 2(N); warp tile
// 32x64. 2 CTAs/SM. smem rows 128B; swizzle: (seg*16) ^ ((row&7)<<4).
// ---------------------------------------------------------------------------
__device__ __forceinline__ void load_stage_half(uint32_t sbase, int s, int chunk,
                                                int m0, int n0, int tid, int half) {
    uint32_t st = sbase + (uint32_t)s * STAGE_BYTES;
    const __half* gA = g_x + (size_t)m0 * IN_F + chunk * BK;
    const __half* gB = g_w + (size_t)n0 * IN_F + chunk * BK;
    #pragma unroll
    for (int it = half * 2; it < half * 2 + 2; ++it) {
        int u = tid + it * 256;                  // 0..1023
        int r = u >> 3, seg = u & 7;             // row, 16B-seg within 128B row
        uint32_t so = (uint32_t)(r * 128) + (uint32_t)((seg * 16) ^ ((r & 7) << 4));
        cp_async16(st + so,         gA + (size_t)r * IN_F + seg * 8);
        cp_async16(st + OFF_B + so, gB + (size_t)r * IN_F + seg * 8);
    }
}

__global__ void __launch_bounds__(256, 2)
gemm_kernel(const float* __restrict__ bias, float* __restrict__ out) {
    extern __shared__ char smem[];
    const uint32_t sbase = smem_u32(smem);
    const int tid  = threadIdx.x;
    const int wid  = tid >> 5;
    const int lane = tid & 31;
    const int bid  = blockIdx.x;
    const int n0 = (bid & (GRID_N - 1)) * BN;    // n-fast: W slab stays in L2
    const int m0 = (bid / GRID_N) * BM;

    const int wm = wid >> 1;                     // 0..3
    const int wn = wid & 1;                      // 0..1
    const int g  = lane >> 2;                    // 0..7
    const int t  = lane & 3;                     // 0..3

    // ldmatrix lane roles
    const int mtx = lane >> 3;                   // matrix index 0..3
    const int rr  = lane & 7;                    // row within matrix
    const uint32_t swz = (uint32_t)rr << 4;      // XOR swizzle for this row

    // A: matrix m -> rows (wm*32 + mi*16 + (m&1)*8 + rr), k-half (m>>1)
    const uint32_t aRowOff = (uint32_t)((wm * 32 + (mtx & 1) * 8 + rr) * 128);
    const uint32_t kbA = (uint32_t)((mtx >> 1) * 16);
    // B: matrix m -> rows (wn*64 + jp*16 + (m>>1)*8 + rr), k-half (m&1)
    const uint32_t bRowOff = (uint32_t)((wn * 64 + (mtx >> 1) * 8 + rr) * 128) + OFF_B;
    const uint32_t kbB = (uint32_t)((mtx & 1) * 16);

    float acc[2][8][4];
    #pragma unroll
    for (int i = 0; i < 2; ++i)
        #pragma unroll
        for (int j = 0; j < 8; ++j)
            #pragma unroll
            for (int c = 0; c < 4; ++c) acc[i][j][c] = 0.0f;

    #pragma unroll
    for (int c = 0; c < STAGES - 1; ++c) {
        load_stage_half(sbase, c, c, m0, n0, tid, 0);
        load_stage_half(sbase, c, c, m0, n0, tid, 1);
        CP_COMMIT();
    }

    int s_cons = 0, s_prod = STAGES - 1;

    #pragma unroll 1
    for (int i = 0; i < NCHUNK; ++i) {
        CP_WAIT(STAGES - 2);                     // chunk i resident
        __syncthreads();
        const bool refill = (i + STAGES - 1 < NCHUNK);
        if (refill) load_stage_half(sbase, s_prod, i + STAGES - 1, m0, n0, tid, 0);

        const uint32_t st = sbase + (uint32_t)s_cons * STAGE_BYTES;
        if (++s_cons == STAGES) s_cons = 0;

        #pragma unroll
        for (int ks = 0; ks < 4; ++ks) {         // k16 steps; 32B per step
            if (ks == 2) {                       // second refill half + commit
                if (refill) {
                    load_stage_half(sbase, s_prod, i + STAGES - 1, m0, n0, tid, 1);
                    if (++s_prod == STAGES) s_prod = 0;
                }
                CP_COMMIT();
            }
            const uint32_t colA = ((uint32_t)(ks * 32) + kbA) ^ swz;
            const uint32_t colB = ((uint32_t)(ks * 32) + kbB) ^ swz;
            uint32_t ar[2][4];
            LDSM4(ar[0], st + aRowOff + colA);              // mi=0 (rows +0)
            LDSM4(ar[1], st + aRowOff + 16 * 128 + colA);   // mi=1 (rows +16)
            #pragma unroll
            for (int jp = 0; jp < 4; ++jp) {     // regs 0,1 = j even; 2,3 = j odd
                uint32_t bq[4];
                LDSM4(bq, st + bRowOff + (uint32_t)(jp * 16 * 128) + colB);
                MMA_F16(acc[0][jp * 2],     ar[0], bq[0], bq[1]);
                MMA_F16(acc[1][jp * 2],     ar[1], bq[0], bq[1]);
                MMA_F16(acc[0][jp * 2 + 1], ar[0], bq[2], bq[3]);
                MMA_F16(acc[1][jp * 2 + 1], ar[1], bq[2], bq[3]);
            }
        }
    }

    // Epilogue: c0/c1 at (row, 2t), c2/c3 at (row+8, 2t); add bias, float2 stores
    #pragma unroll
    for (int mi = 0; mi < 2; ++mi) {
        const int row0 = m0 + wm * 32 + mi * 16 + g;
        #pragma unroll
        for (int j = 0; j < 8; ++j) {
            const int col = n0 + wn * 64 + j * 8 + t * 2;
            const float2 b2 = *reinterpret_cast<const float2*>(bias + col);
            float2 v0, v1;
            v0.x = acc[mi][j][0] + b2.x;  v0.y = acc[mi][j][1] + b2.y;
            v1.x = acc[mi][j][2] + b2.x;  v1.y = acc[mi][j][3] + b2.y;
            *reinterpret_cast<float2*>(out + (size_t)row0 * OUT_F + col) = v0;
            *reinterpret_cast<float2*>(out + (size_t)(row0 + 8) * OUT_F + col) = v1;
        }
    }
}

// ---------------------------------------------------------------------------
// Launch
// ---------------------------------------------------------------------------
extern "C" void kernel_launch(void* const* d_in, const int* in_sizes, int n_in,
                              void* d_out, int out_size) {
    const float* x    = (const float*)d_in[0];
    const int*   wp   = (const int*)d_in[1];
    const float* ws   = (const float*)d_in[2];
    const int*   perm = (const int*)d_in[3];
    const float* bias = (const float*)d_in[4];
    float* out = (float*)d_out;

    inv_perm_kernel<<<IN_F / 256, 256>>>(perm);
    prep_kernel<<<OUT_F + XBLOCKS, 256>>>((const float4*)x, wp, ws);

    cudaFuncSetAttribute(gemm_kernel, cudaFuncAttributeMaxDynamicSharedMemorySize,
                         GEMM_SMEM);
    gemm_kernel<<<GRID_M * GRID_N, 256, GEMM_SMEM>>>(bias, out);
}